// round 8
// baseline (speedup 1.0000x reference)
#include <cuda_runtime.h>
#include <cuda_bf16.h>
#include <cuda_fp16.h>
#include <cstdint>

#define D_MODELX 1024
#define NUM_HEADSX 16
#define D_HEADX 64
#define BATCHX 4
#define SEQX 2048
#define M_TOK (BATCHX * SEQX)    // 8192
#define NZ (BATCHX * NUM_HEADSX) // 64

// ---- static device scratch ----
__device__ __nv_bfloat16 g_xh[(size_t)M_TOK * D_MODELX];
__device__ __nv_bfloat16 g_xl[(size_t)M_TOK * D_MODELX];
__device__ __nv_bfloat16 g_wh[(size_t)D_MODELX * D_MODELX];
__device__ __nv_bfloat16 g_wl[(size_t)D_MODELX * D_MODELX];
__device__ __nv_bfloat16 g_Qh[(size_t)M_TOK * D_MODELX];
__device__ __nv_bfloat16 g_Ql[(size_t)M_TOK * D_MODELX];
__device__ __nv_bfloat16 g_Kh[(size_t)M_TOK * D_MODELX];
__device__ __nv_bfloat16 g_Kl[(size_t)M_TOK * D_MODELX];
__device__ __half g_Vth[(size_t)M_TOK * D_MODELX];  // [Z][64][2048] fp16 hi
__device__ __half g_Vtl[(size_t)M_TOK * D_MODELX];  // [Z][64][2048] fp16 lo
__device__ __nv_bfloat16 g_Oh[(size_t)M_TOK * D_MODELX];
__device__ __nv_bfloat16 g_Ol[(size_t)M_TOK * D_MODELX];
__device__ __half g_P[(size_t)NZ * SEQX * SEQX];    // 0.5 GiB raw fp16 scores
__device__ float  g_rmax[(size_t)NZ * SEQX];
__device__ float  g_rinv[(size_t)NZ * SEQX];

__device__ __forceinline__ unsigned pack_bf2(float x, float y) {
    __nv_bfloat162 t = __floats2bfloat162_rn(x, y);
    return *reinterpret_cast<unsigned*>(&t);
}

__device__ __forceinline__ unsigned smem_u32(const void* p) {
    return (unsigned)__cvta_generic_to_shared(p);
}

#define LDSM_X4(r0, r1, r2, r3, addr)                                         \
    asm volatile("ldmatrix.sync.aligned.m8n8.x4.shared.b16 {%0,%1,%2,%3}, [%4];" \
        : "=r"(r0), "=r"(r1), "=r"(r2), "=r"(r3) : "r"(addr))

#define MMA_BF16(c, a0, a1, a2, a3, b0, b1)                                   \
    asm volatile(                                                             \
        "mma.sync.aligned.m16n8k16.row.col.f32.bf16.bf16.f32 "                \
        "{%0,%1,%2,%3},{%4,%5,%6,%7},{%8,%9},{%0,%1,%2,%3};"                  \
        : "+f"(c[0]), "+f"(c[1]), "+f"(c[2]), "+f"(c[3])                      \
        : "r"(a0), "r"(a1), "r"(a2), "r"(a3), "r"(b0), "r"(b1))

#define MMA_F16(c, a0, a1, a2, a3, b0, b1)                                    \
    asm volatile(                                                             \
        "mma.sync.aligned.m16n8k16.row.col.f32.f16.f16.f32 "                  \
        "{%0,%1,%2,%3},{%4,%5,%6,%7},{%8,%9},{%0,%1,%2,%3};"                  \
        : "+f"(c[0]), "+f"(c[1]), "+f"(c[2]), "+f"(c[3])                      \
        : "r"(a0), "r"(a1), "r"(a2), "r"(a3), "r"(b0), "r"(b1))

// ============================================================================
// split: fp32 -> bf16 hi + bf16 lo
// ============================================================================
__global__ __launch_bounds__(256)
void split_kernel(const float4* __restrict__ src,
                  __nv_bfloat16* __restrict__ dh,
                  __nv_bfloat16* __restrict__ dl)
{
    int i = blockIdx.x * 256 + threadIdx.x;
    float4 v = src[i];
    float h0 = __bfloat162float(__float2bfloat16_rn(v.x));
    float h1 = __bfloat162float(__float2bfloat16_rn(v.y));
    float h2 = __bfloat162float(__float2bfloat16_rn(v.z));
    float h3 = __bfloat162float(__float2bfloat16_rn(v.w));
    uint2 H, L;
    H.x = pack_bf2(v.x, v.y); H.y = pack_bf2(v.z, v.w);
    L.x = pack_bf2(v.x - h0, v.y - h1); L.y = pack_bf2(v.z - h2, v.w - h3);
    *(uint2*)&dh[(size_t)i * 4] = H;
    *(uint2*)&dl[(size_t)i * 4] = L;
}

// ============================================================================
// Pure pre-split bf16 NT GEMM: C = A @ B^T + bias. lda=ldb=ldc=1024, K=1024.
// MODE 0: fp32 out + bias (output projection)
// MODE 3: V projection, transposed fp16 hi/lo store into [Z][64][2048]
// MODE 5: Q/K projection, bf16 hi/lo out + bias
// Block tile 128x64x32, 256 threads (8 warps 4x2), warp tile 32x32, ldmatrix.
// ============================================================================
template <int MODE>
__global__ __launch_bounds__(256)
void proj_gemm(const __nv_bfloat16* __restrict__ Ah, const __nv_bfloat16* __restrict__ Al,
               const __nv_bfloat16* __restrict__ Bh, const __nv_bfloat16* __restrict__ Bl,
               float* __restrict__ C,
               void* __restrict__ Chv, void* __restrict__ Clv,
               const float* __restrict__ bias)
{
    constexpr int BM = 128, BN = 64, BK = 32;
    constexpr int SA = 40;
    constexpr int LD = D_MODELX;

    __shared__ __align__(16) __nv_bfloat16 AsH[BM * SA];
    __shared__ __align__(16) __nv_bfloat16 AsL[BM * SA];
    __shared__ __align__(16) __nv_bfloat16 BsH[BN * SA];
    __shared__ __align__(16) __nv_bfloat16 BsL[BN * SA];

    const int tid  = threadIdx.x;
    const int m0   = blockIdx.y * BM;
    const int n0   = blockIdx.x * BN;
    const int warp = tid >> 5, lane = tid & 31;
    const int wm = (warp & 3) * 32;
    const int wn = (warp >> 2) * 32;
    const int gr = lane >> 2;
    const int gc = lane & 3;
    const int ti = lane >> 3, ri = lane & 7;

    unsigned aHb[2], aLb[2], bHb[2], bLb[2];
    #pragma unroll
    for (int mi = 0; mi < 2; mi++) {
        int row = wm + mi * 16 + (ti & 1) * 8 + ri;
        int col = (ti >> 1) * 8;
        aHb[mi] = smem_u32(&AsH[row * SA + col]);
        aLb[mi] = smem_u32(&AsL[row * SA + col]);
    }
    #pragma unroll
    for (int nip = 0; nip < 2; nip++) {
        int row = wn + (nip * 2 + (ti >> 1)) * 8 + ri;
        int col = (ti & 1) * 8;
        bHb[nip] = smem_u32(&BsH[row * SA + col]);
        bLb[nip] = smem_u32(&BsL[row * SA + col]);
    }

    float acc[2][4][4] = {};
    uint4 pah[2], pal[2], pbh, pbl;

    // prefetch tile 0 (A: 2 chunks/thread/buffer, B: 1)
    {
        #pragma unroll
        for (int i = 0; i < 2; i++) {
            int idx = tid + i * 256, row = idx >> 2, c8 = idx & 3;
            size_t off = (size_t)(m0 + row) * LD + c8 * 8;
            pah[i] = *(const uint4*)(Ah + off);
            pal[i] = *(const uint4*)(Al + off);
        }
        int row = tid >> 2, c8 = tid & 3;
        size_t off = (size_t)(n0 + row) * LD + c8 * 8;
        pbh = *(const uint4*)(Bh + off);
        pbl = *(const uint4*)(Bl + off);
    }

    const int niter = D_MODELX / BK;  // 32
    for (int it = 0; it < niter; ++it) {
        #pragma unroll
        for (int i = 0; i < 2; i++) {
            int idx = tid + i * 256, row = idx >> 2, c8 = idx & 3;
            *(uint4*)&AsH[row * SA + c8 * 8] = pah[i];
            *(uint4*)&AsL[row * SA + c8 * 8] = pal[i];
        }
        {
            int row = tid >> 2, c8 = tid & 3;
            *(uint4*)&BsH[row * SA + c8 * 8] = pbh;
            *(uint4*)&BsL[row * SA + c8 * 8] = pbl;
        }
        __syncthreads();

        if (it + 1 < niter) {
            int k0 = (it + 1) * BK;
            #pragma unroll
            for (int i = 0; i < 2; i++) {
                int idx = tid + i * 256, row = idx >> 2, c8 = idx & 3;
                size_t off = (size_t)(m0 + row) * LD + k0 + c8 * 8;
                pah[i] = *(const uint4*)(Ah + off);
                pal[i] = *(const uint4*)(Al + off);
            }
            int row = tid >> 2, c8 = tid & 3;
            size_t off = (size_t)(n0 + row) * LD + k0 + c8 * 8;
            pbh = *(const uint4*)(Bh + off);
            pbl = *(const uint4*)(Bl + off);
        }

        #pragma unroll
        for (int ks = 0; ks < 2; ks++) {
            const int kb2 = ks * 32;
            unsigned aH[2][4], aL[2][4], bH[2][4], bL[2][4];
            #pragma unroll
            for (int mi = 0; mi < 2; mi++) {
                LDSM_X4(aH[mi][0], aH[mi][1], aH[mi][2], aH[mi][3], aHb[mi] + kb2);
                LDSM_X4(aL[mi][0], aL[mi][1], aL[mi][2], aL[mi][3], aLb[mi] + kb2);
            }
            #pragma unroll
            for (int nip = 0; nip < 2; nip++) {
                LDSM_X4(bH[nip][0], bH[nip][1], bH[nip][2], bH[nip][3], bHb[nip] + kb2);
                LDSM_X4(bL[nip][0], bL[nip][1], bL[nip][2], bL[nip][3], bLb[nip] + kb2);
            }
            #pragma unroll
            for (int mi = 0; mi < 2; mi++)
                #pragma unroll
                for (int nip = 0; nip < 2; nip++)
                    #pragma unroll
                    for (int hh = 0; hh < 2; hh++) {
                        int ni = nip * 2 + hh;
                        unsigned b0 = bH[nip][hh * 2], b1 = bH[nip][hh * 2 + 1];
                        unsigned l0 = bL[nip][hh * 2], l1 = bL[nip][hh * 2 + 1];
                        MMA_BF16(acc[mi][ni], aH[mi][0], aH[mi][1], aH[mi][2], aH[mi][3], b0, b1);
                        MMA_BF16(acc[mi][ni], aH[mi][0], aH[mi][1], aH[mi][2], aH[mi][3], l0, l1);
                        MMA_BF16(acc[mi][ni], aL[mi][0], aL[mi][1], aL[mi][2], aL[mi][3], b0, b1);
                    }
        }
        __syncthreads();
    }

    #pragma unroll
    for (int mi = 0; mi < 2; mi++)
        #pragma unroll
        for (int ni = 0; ni < 4; ni++) {
            int r = m0 + wm + mi * 16 + gr;
            int c = n0 + wn + ni * 8 + gc * 2;
            float* cc = acc[mi][ni];
            if (MODE == 3) {
                __half* Ch = (__half*)Chv;
                __half* Cl = (__half*)Clv;
                int b = r >> 11, s = r & 2047;
                int h = c >> 6, d = c & 63;
                float b0 = bias[c], b1 = bias[c + 1];
                float v00 = cc[0] + b0, v01 = cc[1] + b1;
                float v10 = cc[2] + b0, v11 = cc[3] + b1;
                size_t base = ((size_t)(b * 16 + h) * 64 + d) * 2048;
                __half h00 = __float2half_rn(v00);
                __half h01 = __float2half_rn(v01);
                __half h10 = __float2half_rn(v10);
                __half h11 = __float2half_rn(v11);
                Ch[base + s]            = h00;
                Ch[base + 2048 + s]     = h01;
                Ch[base + s + 8]        = h10;
                Ch[base + 2048 + s + 8] = h11;
                Cl[base + s]            = __float2half_rn(v00 - __half2float(h00));
                Cl[base + 2048 + s]     = __float2half_rn(v01 - __half2float(h01));
                Cl[base + s + 8]        = __float2half_rn(v10 - __half2float(h10));
                Cl[base + 2048 + s + 8] = __float2half_rn(v11 - __half2float(h11));
            } else if (MODE == 5) {
                __nv_bfloat16* Ch = (__nv_bfloat16*)Chv;
                __nv_bfloat16* Cl = (__nv_bfloat16*)Clv;
                float b0 = bias[c], b1 = bias[c + 1];
                float v00 = cc[0] + b0, v01 = cc[1] + b1;
                float v10 = cc[2] + b0, v11 = cc[3] + b1;
                float h00 = __bfloat162float(__float2bfloat16_rn(v00));
                float h01 = __bfloat162float(__float2bfloat16_rn(v01));
                float h10 = __bfloat162float(__float2bfloat16_rn(v10));
                float h11 = __bfloat162float(__float2bfloat16_rn(v11));
                size_t o0 = (size_t)r * D_MODELX + c;
                size_t o1 = (size_t)(r + 8) * D_MODELX + c;
                *(unsigned*)&Ch[o0] = pack_bf2(v00, v01);
                *(unsigned*)&Ch[o1] = pack_bf2(v10, v11);
                *(unsigned*)&Cl[o0] = pack_bf2(v00 - h00, v01 - h01);
                *(unsigned*)&Cl[o1] = pack_bf2(v10 - h10, v11 - h11);
            } else {
                float b0 = bias[c], b1 = bias[c + 1];
                float2 v0 = make_float2(cc[0] + b0, cc[1] + b1);
                float2 v1 = make_float2(cc[2] + b0, cc[3] + b1);
                *(float2*)&C[(size_t)r * D_MODELX + c]       = v0;
                *(float2*)&C[(size_t)(r + 8) * D_MODELX + c] = v1;
            }
        }
}

// ============================================================================
// Scores: P[z] = fp16((Q_h @ K_h^T)/8), pre-split bf16, K=64 single load.
// Block tile 128x128, 8 warps (4M x 2N), warp tile 32x64. ldmatrix fragments.
// ============================================================================
__global__ __launch_bounds__(256)
void scores_gemm(const __nv_bfloat16* __restrict__ Qh, const __nv_bfloat16* __restrict__ Ql,
                 const __nv_bfloat16* __restrict__ Kh, const __nv_bfloat16* __restrict__ Kl,
                 __half* __restrict__ P)
{
    constexpr int SA = 72;
    __shared__ __align__(16) __nv_bfloat16 AsH[128 * SA];
    __shared__ __align__(16) __nv_bfloat16 AsL[128 * SA];
    __shared__ __align__(16) __nv_bfloat16 BsH[128 * SA];
    __shared__ __align__(16) __nv_bfloat16 BsL[128 * SA];

    const int z = blockIdx.z, b = z >> 4, h = z & 15;
    const size_t qo = (size_t)b * SEQX * D_MODELX + h * D_HEADX;
    Qh += qo; Ql += qo; Kh += qo; Kl += qo;
    P += (size_t)z * SEQX * SEQX;

    const int tid  = threadIdx.x;
    const int m0   = blockIdx.y * 128;
    const int n0   = blockIdx.x * 128;
    const int warp = tid >> 5, lane = tid & 31;
    const int wm = (warp & 3) * 32;
    const int wn = (warp >> 2) * 64;
    const int gr = lane >> 2;
    const int gc = lane & 3;
    const int ti = lane >> 3, ri = lane & 7;

    #pragma unroll
    for (int i = 0; i < 4; i++) {
        int idx = tid + i * 256, row = idx >> 3, c8 = idx & 7;
        size_t oa = (size_t)(m0 + row) * D_MODELX + c8 * 8;
        size_t ob = (size_t)(n0 + row) * D_MODELX + c8 * 8;
        *(uint4*)&AsH[row * SA + c8 * 8] = *(const uint4*)(Qh + oa);
        *(uint4*)&AsL[row * SA + c8 * 8] = *(const uint4*)(Ql + oa);
        *(uint4*)&BsH[row * SA + c8 * 8] = *(const uint4*)(Kh + ob);
        *(uint4*)&BsL[row * SA + c8 * 8] = *(const uint4*)(Kl + ob);
    }
    __syncthreads();

    unsigned aHb[2], aLb[2], bHb[4], bLb[4];
    #pragma unroll
    for (int mi = 0; mi < 2; mi++) {
        int row = wm + mi * 16 + (ti & 1) * 8 + ri;
        int col = (ti >> 1) * 8;
        aHb[mi] = smem_u32(&AsH[row * SA + col]);
        aLb[mi] = smem_u32(&AsL[row * SA + col]);
    }
    #pragma unroll
    for (int nip = 0; nip < 4; nip++) {
        int row = wn + (nip * 2 + (ti >> 1)) * 8 + ri;
        int col = (ti & 1) * 8;
        bHb[nip] = smem_u32(&BsH[row * SA + col]);
        bLb[nip] = smem_u32(&BsL[row * SA + col]);
    }

    float acc[2][8][4] = {};

    #pragma unroll
    for (int ks = 0; ks < 4; ks++) {
        const int kb2 = ks * 32;
        unsigned aH[2][4], aL[2][4], bH[4][4], bL[4][4];
        #pragma unroll
        for (int mi = 0; mi < 2; mi++) {
            LDSM_X4(aH[mi][0], aH[mi][1], aH[mi][2], aH[mi][3], aHb[mi] + kb2);
            LDSM_X4(aL[mi][0], aL[mi][1], aL[mi][2], aL[mi][3], aLb[mi] + kb2);
        }
        #pragma unroll
        for (int nip = 0; nip < 4; nip++) {
            LDSM_X4(bH[nip][0], bH[nip][1], bH[nip][2], bH[nip][3], bHb[nip] + kb2);
            LDSM_X4(bL[nip][0], bL[nip][1], bL[nip][2], bL[nip][3], bLb[nip] + kb2);
        }
        #pragma unroll
        for (int nip = 0; nip < 4; nip++)
            #pragma unroll
            for (int hh = 0; hh < 2; hh++) {
                int ni = nip * 2 + hh;
                unsigned b0 = bH[nip][hh * 2], b1 = bH[nip][hh * 2 + 1];
                unsigned l0 = bL[nip][hh * 2], l1 = bL[nip][hh * 2 + 1];
                #pragma unroll
                for (int mi = 0; mi < 2; mi++) {
                    MMA_BF16(acc[mi][ni], aH[mi][0], aH[mi][1], aH[mi][2], aH[mi][3], b0, b1);
                    MMA_BF16(acc[mi][ni], aH[mi][0], aH[mi][1], aH[mi][2], aH[mi][3], l0, l1);
                    MMA_BF16(acc[mi][ni], aL[mi][0], aL[mi][1], aL[mi][2], aL[mi][3], b0, b1);
                }
            }
    }

    #pragma unroll
    for (int mi = 0; mi < 2; mi++)
        #pragma unroll
        for (int ni = 0; ni < 8; ni++) {
            int r = m0 + wm + mi * 16 + gr;
            int c = n0 + wn + ni * 8 + gc * 2;
            float* cc = acc[mi][ni];
            __half2 h0 = __floats2half2_rn(cc[0] * 0.125f, cc[1] * 0.125f);
            __half2 h1 = __floats2half2_rn(cc[2] * 0.125f, cc[3] * 0.125f);
            __stcs((int*)&P[(size_t)r * SEQX + c], *(int*)&h0);
            __stcs((int*)&P[(size_t)(r + 8) * SEQX + c], *(int*)&h1);
        }
}

// ============================================================================
// stats + head-average (no P rewrite), streaming loads
// ============================================================================
__global__ __launch_bounds__(256)
void stats_avg_kernel(const __half* __restrict__ P, float* __restrict__ avg,
                      float* __restrict__ rmax, float* __restrict__ rinv)
{
    __shared__ float red[8];
    const int bq = blockIdx.x;
    const int t  = threadIdx.x;
    const int b  = bq >> 11;
    const int q  = bq & 2047;

    float avgacc[8] = {};

    for (int h = 0; h < NUM_HEADSX; ++h) {
        const int z = b * 16 + h;
        const unsigned* p2 = (const unsigned*)(P + ((size_t)z * SEQX + q) * SEQX);

        float2 v[4];
        float mx = -1e30f;
        #pragma unroll
        for (int i = 0; i < 4; i++) {
            unsigned u = __ldcs(p2 + t + i * 256);
            v[i] = __half22float2(*reinterpret_cast<__half2*>(&u));
            mx = fmaxf(mx, fmaxf(v[i].x, v[i].y));
        }
        #pragma unroll
        for (int o = 16; o > 0; o >>= 1)
            mx = fmaxf(mx, __shfl_xor_sync(0xffffffffu, mx, o));
        if ((t & 31) == 0) red[t >> 5] = mx;
        __syncthreads();
        float bm = red[0];
        #pragma unroll
        for (int w = 1; w < 8; w++) bm = fmaxf(bm, red[w]);
        __syncthreads();

        float s = 0.f;
        #pragma unroll
        for (int i = 0; i < 4; i++) {
            v[i].x = __expf(v[i].x - bm);
            v[i].y = __expf(v[i].y - bm);
            s += v[i].x + v[i].y;
        }
        #pragma unroll
        for (int o = 16; o > 0; o >>= 1)
            s += __shfl_xor_sync(0xffffffffu, s, o);
        if ((t & 31) == 0) red[t >> 5] = s;
        __syncthreads();
        float bs = 0.f;
        #pragma unroll
        for (int w = 0; w < 8; w++) bs += red[w];
        float inv = 1.0f / bs;
        if (t == 0) {
            rmax[(size_t)z * SEQX + q] = bm;
            rinv[(size_t)z * SEQX + q] = inv;
        }

        #pragma unroll
        for (int i = 0; i < 4; i++) {
            avgacc[2 * i]     += v[i].x * inv;
            avgacc[2 * i + 1] += v[i].y * inv;
        }
        __syncthreads();
    }

    float2* a2 = (float2*)(avg + (size_t)bq * SEQX);
    #pragma unroll
    for (int i = 0; i < 4; i++)
        __stcs(a2 + t + i * 256,
               make_float2(avgacc[2 * i] * (1.0f / NUM_HEADSX),
                           avgacc[2 * i + 1] * (1.0f / NUM_HEADSX)));
}

// ============================================================================
// AV: O_h = softmax(P)[z] @ Vt_h^T, exp on load, fp16 hi/lo V, ldmatrix frags.
// Writes bf16 hi/lo O for the output projection.
// ============================================================================
__global__ __launch_bounds__(256)
void av_gemm(const __half* __restrict__ P,
             const __half* __restrict__ Vh, const __half* __restrict__ Vl,
             const float* __restrict__ rmax, const float* __restrict__ rinv,
             __nv_bfloat16* __restrict__ Oh, __nv_bfloat16* __restrict__ Ol)
{
    constexpr int BM = 128, BK = 64;
    constexpr int SA = 72;

    __shared__ __align__(16) __half As[BM * SA];
    __shared__ __align__(16) __half BsH[64 * SA];
    __shared__ __align__(16) __half BsL[64 * SA];
    __shared__ float sm_m[BM], sm_i[BM];

    const int z = blockIdx.z, b = z >> 4, h = z & 15;
    P  += (size_t)z * SEQX * SEQX;
    Vh += (size_t)z * D_HEADX * SEQX;
    Vl += (size_t)z * D_HEADX * SEQX;
    Oh += (size_t)b * SEQX * D_MODELX + h * D_HEADX;
    Ol += (size_t)b * SEQX * D_MODELX + h * D_HEADX;
    rmax += (size_t)z * SEQX;
    rinv += (size_t)z * SEQX;

    const int tid  = threadIdx.x;
    const int m0   = blockIdx.y * BM;
    const int warp = tid >> 5, lane = tid & 31;
    const int wm = (warp & 3) * 32;
    const int wn = (warp >> 2) * 32;
    const int gr = lane >> 2;
    const int gc = lane & 3;
    const int ti = lane >> 3, ri = lane & 7;

    if (tid < BM) { sm_m[tid] = rmax[m0 + tid]; sm_i[tid] = rinv[m0 + tid]; }
    __syncthreads();

    unsigned ab[2], bHb[2], bLb[2];
    #pragma unroll
    for (int mi = 0; mi < 2; mi++) {
        int row = wm + mi * 16 + (ti & 1) * 8 + ri;
        int col = (ti >> 1) * 8;
        ab[mi] = smem_u32(&As[row * SA + col]);
    }
    #pragma unroll
    for (int nip = 0; nip < 2; nip++) {
        int row = wn + (nip * 2 + (ti >> 1)) * 8 + ri;
        int col = (ti & 1) * 8;
        bHb[nip] = smem_u32(&BsH[row * SA + col]);
        bLb[nip] = smem_u32(&BsL[row * SA + col]);
    }

    float acc[2][4][4] = {};
    uint4 pa[4], pbh[2], pbl[2];

    {
        #pragma unroll
        for (int i = 0; i < 4; i++) {
            int idx = tid + i * 256, row = idx >> 3, c8 = idx & 7;
            pa[i] = __ldcs((const uint4*)(P + (size_t)(m0 + row) * SEQX + c8 * 8));
        }
        #pragma unroll
        for (int i = 0; i < 2; i++) {
            int idx = tid + i * 256, row = idx >> 3, c8 = idx & 7;
            pbh[i] = *(const uint4*)(Vh + (size_t)row * SEQX + c8 * 8);
            pbl[i] = *(const uint4*)(Vl + (size_t)row * SEQX + c8 * 8);
        }
    }

    const int niter = SEQX / BK;  // 32
    for (int it = 0; it < niter; ++it) {
        #pragma unroll
        for (int i = 0; i < 4; i++) {
            int idx = tid + i * 256, row = idx >> 3, c8 = idx & 7;
            float m = sm_m[row], inv = sm_i[row];
            const __half2* hp = (const __half2*)&pa[i];
            uint4 out;
            unsigned* op = (unsigned*)&out;
            #pragma unroll
            for (int j = 0; j < 4; j++) {
                float2 f = __half22float2(hp[j]);
                __half2 e = __floats2half2_rn(__expf(f.x - m) * inv,
                                              __expf(f.y - m) * inv);
                op[j] = *(unsigned*)&e;
            }
            *(uint4*)&As[row * SA + c8 * 8] = out;
        }
        #pragma unroll
        for (int i = 0; i < 2; i++) {
            int idx = tid + i * 256, row = idx >> 3, c8 = idx & 7;
            *(uint4*)&BsH[row * SA + c8 * 8] = pbh[i];
            *(uint4*)&BsL[row * SA + c8 * 8] = pbl[i];
        }
        __syncthreads();

        if (it + 1 < niter) {
            int k0 = (it + 1) * BK;
            #pragma unroll
            for (int i = 0; i < 4; i++) {
                int idx = tid + i * 256, row = idx >> 3, c8 = idx & 7;
                pa[i] = __ldcs((const uint4*)(P + (size_t)(m0 + row) * SEQX + k0 + c8 * 8));
            }
            #pragma unroll
            for (int i = 0; i < 2; i++) {
                int idx = tid + i * 256, row = idx >> 3, c8 = idx & 7;
                pbh[i] = *(const uint4*)(Vh + (size_t)row * SEQX + k0 + c8 * 8);
                pbl[i] = *(const uint4*)(Vl + (size_t)row * SEQX + k0 + c8 * 8);
            }
        }

        #pragma unroll
        for (int ks = 0; ks < 4; ks++) {
            const int kb2 = ks * 32;
            unsigned a[2][4], bH[2][4], bL[2][4];
            #pragma unroll
            for (int mi = 0; mi < 2; mi++)
                LDSM_X4(a[mi][0], a[mi][1], a[mi][2], a[mi][3], ab[mi] + kb2);
            #pragma unroll
            for (int nip = 0; nip < 2; nip++) {
                LDSM_X4(bH[nip][0], bH[nip][1], bH[nip][2], bH[nip][3], bHb[nip] + kb2);
                LDSM_X4(bL[nip][0], bL[nip][1], bL[nip][2], bL[nip][3], bLb[nip] + kb2);
            }
            #pragma unroll
            for (int mi = 0; mi < 2; mi++)
                #pragma unroll
                for (int nip = 0; nip < 2; nip++)
                    #pragma unroll
                    for (int hh = 0; hh < 2; hh++) {
                        int ni = nip * 2 + hh;
                        MMA_F16(acc[mi][ni], a[mi][0], a[mi][1], a[mi][2], a[mi][3],
                                bH[nip][hh * 2], bH[nip][hh * 2 + 1]);
                        MMA_F16(acc[mi][ni], a[mi][0], a[mi][1], a[mi][2], a[mi][3],
                                bL[nip][hh * 2], bL[nip][hh * 2 + 1]);
                    }
        }
        __syncthreads();
    }

    #pragma unroll
    for (int mi = 0; mi < 2; mi++)
        #pragma unroll
        for (int ni = 0; ni < 4; ni++) {
            int r = m0 + wm + mi * 16 + gr;
            int c = wn + ni * 8 + gc * 2;
            float* cc = acc[mi][ni];
            float v00 = cc[0], v01 = cc[1], v10 = cc[2], v11 = cc[3];
            float h00 = __bfloat162float(__float2bfloat16_rn(v00));
            float h01 = __bfloat162float(__float2bfloat16_rn(v01));
            float h10 = __bfloat162float(__float2bfloat16_rn(v10));
            float h11 = __bfloat162float(__float2bfloat16_rn(v11));
            size_t o0 = (size_t)r * D_MODELX + c;
            size_t o1 = (size_t)(r + 8) * D_MODELX + c;
            *(unsigned*)&Oh[o0] = pack_bf2(v00, v01);
            *(unsigned*)&Oh[o1] = pack_bf2(v10, v11);
            *(unsigned*)&Ol[o0] = pack_bf2(v00 - h00, v01 - h01);
            *(unsigned*)&Ol[o1] = pack_bf2(v10 - h10, v11 - h11);
        }
}

// ============================================================================
// launch
// ============================================================================
extern "C" void kernel_launch(void* const* d_in, const int* in_sizes, int n_in,
                              void* d_out, int out_size)
{
    const float* x_q = (const float*)d_in[0];
    const float* x_k = (const float*)d_in[1];
    const float* x_v = (const float*)d_in[2];
    const float* Wq  = (const float*)d_in[3];
    const float* bq  = (const float*)d_in[4];
    const float* Wk  = (const float*)d_in[5];
    const float* bk  = (const float*)d_in[6];
    const float* Wv  = (const float*)d_in[7];
    const float* bv  = (const float*)d_in[8];
    const float* Wo  = (const float*)d_in[9];
    const float* bo  = (const float*)d_in[10];

    float* out = (float*)d_out;
    float* avg = out + (size_t)M_TOK * D_MODELX;

    __nv_bfloat16 *xh, *xl, *wh, *wl, *Qh, *Ql, *Kh, *Kl, *Oh, *Ol;
    __half *Vth, *Vtl, *P;
    float *rmax, *rinv;
    cudaGetSymbolAddress((void**)&xh, g_xh);
    cudaGetSymbolAddress((void**)&xl, g_xl);
    cudaGetSymbolAddress((void**)&wh, g_wh);
    cudaGetSymbolAddress((void**)&wl, g_wl);
    cudaGetSymbolAddress((void**)&Qh, g_Qh);
    cudaGetSymbolAddress((void**)&Ql, g_Ql);
    cudaGetSymbolAddress((void**)&Kh, g_Kh);
    cudaGetSymbolAddress((void**)&Kl, g_Kl);
    cudaGetSymbolAddress((void**)&Vth, g_Vth);
    cudaGetSymbolAddress((void**)&Vtl, g_Vtl);
    cudaGetSymbolAddress((void**)&Oh, g_Oh);
    cudaGetSymbolAddress((void**)&Ol, g_Ol);
    cudaGetSymbolAddress((void**)&P, g_P);
    cudaGetSymbolAddress((void**)&rmax, g_rmax);
    cudaGetSymbolAddress((void**)&rinv, g_rinv);

    dim3 blk(256);
    const int nxb = M_TOK * D_MODELX / 4 / 256;      // 8192 blocks
    const int nwb = D_MODELX * D_MODELX / 4 / 256;   // 1024 blocks
    dim3 gproj(D_MODELX / 64, M_TOK / 128, 1);       // (16, 64)

    // ---- Q projection ----
    split_kernel<<<nxb, blk>>>((const float4*)x_q, xh, xl);
    split_kernel<<<nwb, blk>>>((const float4*)Wq, wh, wl);
    proj_gemm<5><<<gproj, blk>>>(xh, xl, wh, wl, nullptr, Qh, Ql, bq);
    // ---- K projection ----
    split_kernel<<<nxb, blk>>>((const float4*)x_k, xh, xl);
    split_kernel<<<nwb, blk>>>((const float4*)Wk, wh, wl);
    proj_gemm<5><<<gproj, blk>>>(xh, xl, wh, wl, nullptr, Kh, Kl, bk);
    // ---- V projection (transposed fp16 out) ----
    split_kernel<<<nxb, blk>>>((const float4*)x_v, xh, xl);
    split_kernel<<<nwb, blk>>>((const float4*)Wv, wh, wl);
    proj_gemm<3><<<gproj, blk>>>(xh, xl, wh, wl, nullptr, Vth, Vtl, bv);

    // ---- scores: raw fp16 P = (Q_h @ K_h^T) / 8 ----
    dim3 gsc(SEQX / 128, SEQX / 128, NZ);            // (16, 16, 64)
    scores_gemm<<<gsc, blk>>>(Qh, Ql, Kh, Kl, P);

    // ---- softmax stats + head-average ----
    stats_avg_kernel<<<M_TOK, blk>>>(P, avg, rmax, rinv);

    // ---- AV: bf16 hi/lo O out ----
    dim3 gav(1, SEQX / 128, NZ);                     // (1, 16, 64)
    av_gemm<<<gav, blk>>>(P, Vth, Vtl, rmax, rinv, Oh, Ol);

    // ---- output projection ----
    split_kernel<<<nwb, blk>>>((const float4*)Wo, wh, wl);
    proj_gemm<0><<<gproj, blk>>>(Oh, Ol, wh, wl, out, nullptr, nullptr, bo);
}

// round 10
// speedup vs baseline: 1.1153x; 1.1153x over previous
#include <cuda_runtime.h>
#include <cuda_bf16.h>
#include <cuda_fp16.h>
#include <cstdint>

#define D_MODELX 1024
#define NUM_HEADSX 16
#define D_HEADX 64
#define BATCHX 4
#define SEQX 2048
#define M_TOK (BATCHX * SEQX)    // 8192
#define NZ (BATCHX * NUM_HEADSX) // 64

// ---- static device scratch ----
__device__ __nv_bfloat16 g_Qh[(size_t)M_TOK * D_MODELX];
__device__ __nv_bfloat16 g_Ql[(size_t)M_TOK * D_MODELX];
__device__ __nv_bfloat16 g_Kh[(size_t)M_TOK * D_MODELX];
__device__ __nv_bfloat16 g_Kl[(size_t)M_TOK * D_MODELX];
__device__ __half g_Vth[(size_t)M_TOK * D_MODELX];  // [Z][64][2048] fp16 hi
__device__ __half g_Vtl[(size_t)M_TOK * D_MODELX];  // [Z][64][2048] fp16 lo
__device__ float  g_O[(size_t)M_TOK * D_MODELX];
__device__ __half g_P[(size_t)NZ * SEQX * SEQX];    // 0.5 GiB raw fp16 scores
__device__ float  g_rmax[(size_t)NZ * SEQX];
__device__ float  g_rinv[(size_t)NZ * SEQX];

__device__ __forceinline__ unsigned pack_bf2(float x, float y) {
    __nv_bfloat162 t = __floats2bfloat162_rn(x, y);
    return *reinterpret_cast<unsigned*>(&t);
}

__device__ __forceinline__ unsigned smem_u32(const void* p) {
    return (unsigned)__cvta_generic_to_shared(p);
}

#define LDSM_X4(r0, r1, r2, r3, addr)                                         \
    asm volatile("ldmatrix.sync.aligned.m8n8.x4.shared.b16 {%0,%1,%2,%3}, [%4];" \
        : "=r"(r0), "=r"(r1), "=r"(r2), "=r"(r3) : "r"(addr))

#define MMA_BF16(c, a0, a1, a2, a3, b0, b1)                                   \
    asm volatile(                                                             \
        "mma.sync.aligned.m16n8k16.row.col.f32.bf16.bf16.f32 "                \
        "{%0,%1,%2,%3},{%4,%5,%6,%7},{%8,%9},{%0,%1,%2,%3};"                  \
        : "+f"(c[0]), "+f"(c[1]), "+f"(c[2]), "+f"(c[3])                      \
        : "r"(a0), "r"(a1), "r"(a2), "r"(a3), "r"(b0), "r"(b1))

#define MMA_F16(c, a0, a1, a2, a3, b0, b1)                                    \
    asm volatile(                                                             \
        "mma.sync.aligned.m16n8k16.row.col.f32.f16.f16.f32 "                  \
        "{%0,%1,%2,%3},{%4,%5,%6,%7},{%8,%9},{%0,%1,%2,%3};"                  \
        : "+f"(c[0]), "+f"(c[1]), "+f"(c[2]), "+f"(c[3])                      \
        : "r"(a0), "r"(a1), "r"(a2), "r"(a3), "r"(b0), "r"(b1))

// ============================================================================
// NT bf16-split MMA GEMM (fp32 in, split in-kernel): C = A @ B^T + bias
// MODE 0: fp32 out + bias (output projection)
// MODE 3: V projection, transposed fp16 hi/lo store into [Z][64][2048]
// MODE 5: Q/K projection, bf16 hi/lo out + bias
// Block tile 128x64x32, 256 threads (8 warps 4x2), warp tile 32x32, ldmatrix.
// ============================================================================
template <int MODE>
__global__ __launch_bounds__(256)
void mma_gemm(const float* __restrict__ A,
              const float* __restrict__ B,
              float* __restrict__ C,
              void* __restrict__ Chv, void* __restrict__ Clv,
              int lda, int ldb, int ldc,
              int K, const float* __restrict__ bias)
{
    constexpr int BM = 128, BN = 64, BK = 32;
    constexpr int SA = 40;

    __shared__ __align__(16) __nv_bfloat16 AsH[BM * SA];
    __shared__ __align__(16) __nv_bfloat16 AsL[BM * SA];
    __shared__ __align__(16) __nv_bfloat16 BsH[BN * SA];
    __shared__ __align__(16) __nv_bfloat16 BsL[BN * SA];

    const int tid  = threadIdx.x;
    const int m0   = blockIdx.y * BM;
    const int n0   = blockIdx.x * BN;
    const int warp = tid >> 5, lane = tid & 31;
    const int wm = (warp & 3) * 32;
    const int wn = (warp >> 2) * 32;
    const int gr = lane >> 2;
    const int gc = lane & 3;
    const int ti = lane >> 3, ri = lane & 7;

    unsigned aHb[2], aLb[2], bHb[2], bLb[2];
    #pragma unroll
    for (int mi = 0; mi < 2; mi++) {
        int row = wm + mi * 16 + (ti & 1) * 8 + ri;
        int col = (ti >> 1) * 8;
        aHb[mi] = smem_u32(&AsH[row * SA + col]);
        aLb[mi] = smem_u32(&AsL[row * SA + col]);
    }
    #pragma unroll
    for (int nip = 0; nip < 2; nip++) {
        int row = wn + (nip * 2 + (ti >> 1)) * 8 + ri;
        int col = (ti & 1) * 8;
        bHb[nip] = smem_u32(&BsH[row * SA + col]);
        bLb[nip] = smem_u32(&BsL[row * SA + col]);
    }

    float acc[2][4][4] = {};
    float4 ra[4], rb[2];

    {
        #pragma unroll
        for (int i = 0; i < 4; i++) {
            int idx = tid + i * 256, row = idx >> 3, c4 = idx & 7;
            ra[i] = *(const float4*)(A + (size_t)(m0 + row) * lda + c4 * 4);
        }
        #pragma unroll
        for (int i = 0; i < 2; i++) {
            int idx = tid + i * 256, row = idx >> 3, c4 = idx & 7;
            rb[i] = *(const float4*)(B + (size_t)(n0 + row) * ldb + c4 * 4);
        }
    }

    const int niter = K / BK;
    for (int it = 0; it < niter; ++it) {
        #pragma unroll
        for (int i = 0; i < 4; i++) {
            int idx = tid + i * 256, row = idx >> 3, c4 = idx & 7;
            float v0 = ra[i].x, v1 = ra[i].y, v2 = ra[i].z, v3 = ra[i].w;
            float h0 = __bfloat162float(__float2bfloat16_rn(v0));
            float h1 = __bfloat162float(__float2bfloat16_rn(v1));
            float h2 = __bfloat162float(__float2bfloat16_rn(v2));
            float h3 = __bfloat162float(__float2bfloat16_rn(v3));
            uint2 H, L;
            H.x = pack_bf2(v0, v1); H.y = pack_bf2(v2, v3);
            L.x = pack_bf2(v0 - h0, v1 - h1); L.y = pack_bf2(v2 - h2, v3 - h3);
            *(uint2*)&AsH[row * SA + c4 * 4] = H;
            *(uint2*)&AsL[row * SA + c4 * 4] = L;
        }
        #pragma unroll
        for (int i = 0; i < 2; i++) {
            int idx = tid + i * 256, row = idx >> 3, c4 = idx & 7;
            float v0 = rb[i].x, v1 = rb[i].y, v2 = rb[i].z, v3 = rb[i].w;
            float h0 = __bfloat162float(__float2bfloat16_rn(v0));
            float h1 = __bfloat162float(__float2bfloat16_rn(v1));
            float h2 = __bfloat162float(__float2bfloat16_rn(v2));
            float h3 = __bfloat162float(__float2bfloat16_rn(v3));
            uint2 H, L;
            H.x = pack_bf2(v0, v1); H.y = pack_bf2(v2, v3);
            L.x = pack_bf2(v0 - h0, v1 - h1); L.y = pack_bf2(v2 - h2, v3 - h3);
            *(uint2*)&BsH[row * SA + c4 * 4] = H;
            *(uint2*)&BsL[row * SA + c4 * 4] = L;
        }
        __syncthreads();

        if (it + 1 < niter) {
            int k0 = (it + 1) * BK;
            #pragma unroll
            for (int i = 0; i < 4; i++) {
                int idx = tid + i * 256, row = idx >> 3, c4 = idx & 7;
                ra[i] = *(const float4*)(A + (size_t)(m0 + row) * lda + k0 + c4 * 4);
            }
            #pragma unroll
            for (int i = 0; i < 2; i++) {
                int idx = tid + i * 256, row = idx >> 3, c4 = idx & 7;
                rb[i] = *(const float4*)(B + (size_t)(n0 + row) * ldb + k0 + c4 * 4);
            }
        }

        #pragma unroll
        for (int ks = 0; ks < 2; ks++) {
            const int kb2 = ks * 32;
            unsigned aH[2][4], aL[2][4], bH[2][4], bL[2][4];
            #pragma unroll
            for (int mi = 0; mi < 2; mi++) {
                LDSM_X4(aH[mi][0], aH[mi][1], aH[mi][2], aH[mi][3], aHb[mi] + kb2);
                LDSM_X4(aL[mi][0], aL[mi][1], aL[mi][2], aL[mi][3], aLb[mi] + kb2);
            }
            #pragma unroll
            for (int nip = 0; nip < 2; nip++) {
                LDSM_X4(bH[nip][0], bH[nip][1], bH[nip][2], bH[nip][3], bHb[nip] + kb2);
                LDSM_X4(bL[nip][0], bL[nip][1], bL[nip][2], bL[nip][3], bLb[nip] + kb2);
            }
            #pragma unroll
            for (int mi = 0; mi < 2; mi++)
                #pragma unroll
                for (int nip = 0; nip < 2; nip++)
                    #pragma unroll
                    for (int hh = 0; hh < 2; hh++) {
                        int ni = nip * 2 + hh;
                        unsigned b0 = bH[nip][hh * 2], b1 = bH[nip][hh * 2 + 1];
                        unsigned l0 = bL[nip][hh * 2], l1 = bL[nip][hh * 2 + 1];
                        MMA_BF16(acc[mi][ni], aH[mi][0], aH[mi][1], aH[mi][2], aH[mi][3], b0, b1);
                        MMA_BF16(acc[mi][ni], aH[mi][0], aH[mi][1], aH[mi][2], aH[mi][3], l0, l1);
                        MMA_BF16(acc[mi][ni], aL[mi][0], aL[mi][1], aL[mi][2], aL[mi][3], b0, b1);
                    }
        }
        __syncthreads();
    }

    #pragma unroll
    for (int mi = 0; mi < 2; mi++)
        #pragma unroll
        for (int ni = 0; ni < 4; ni++) {
            int r = m0 + wm + mi * 16 + gr;
            int c = n0 + wn + ni * 8 + gc * 2;
            float* cc = acc[mi][ni];
            if (MODE == 3) {
                __half* Ch = (__half*)Chv;
                __half* Cl = (__half*)Clv;
                int b = r >> 11, s = r & 2047;
                int h = c >> 6, d = c & 63;
                float b0 = bias[c], b1 = bias[c + 1];
                float v00 = cc[0] + b0, v01 = cc[1] + b1;
                float v10 = cc[2] + b0, v11 = cc[3] + b1;
                size_t base = ((size_t)(b * 16 + h) * 64 + d) * 2048;
                __half h00 = __float2half_rn(v00);
                __half h01 = __float2half_rn(v01);
                __half h10 = __float2half_rn(v10);
                __half h11 = __float2half_rn(v11);
                Ch[base + s]            = h00;
                Ch[base + 2048 + s]     = h01;
                Ch[base + s + 8]        = h10;
                Ch[base + 2048 + s + 8] = h11;
                Cl[base + s]            = __float2half_rn(v00 - __half2float(h00));
                Cl[base + 2048 + s]     = __float2half_rn(v01 - __half2float(h01));
                Cl[base + s + 8]        = __float2half_rn(v10 - __half2float(h10));
                Cl[base + 2048 + s + 8] = __float2half_rn(v11 - __half2float(h11));
            } else if (MODE == 5) {
                __nv_bfloat16* Ch = (__nv_bfloat16*)Chv;
                __nv_bfloat16* Cl = (__nv_bfloat16*)Clv;
                float b0 = bias[c], b1 = bias[c + 1];
                float v00 = cc[0] + b0, v01 = cc[1] + b1;
                float v10 = cc[2] + b0, v11 = cc[3] + b1;
                float h00 = __bfloat162float(__float2bfloat16_rn(v00));
                float h01 = __bfloat162float(__float2bfloat16_rn(v01));
                float h10 = __bfloat162float(__float2bfloat16_rn(v10));
                float h11 = __bfloat162float(__float2bfloat16_rn(v11));
                size_t o0 = (size_t)r * ldc + c;
                size_t o1 = (size_t)(r + 8) * ldc + c;
                *(unsigned*)&Ch[o0] = pack_bf2(v00, v01);
                *(unsigned*)&Ch[o1] = pack_bf2(v10, v11);
                *(unsigned*)&Cl[o0] = pack_bf2(v00 - h00, v01 - h01);
                *(unsigned*)&Cl[o1] = pack_bf2(v10 - h10, v11 - h11);
            } else {
                float b0 = 0.f, b1 = 0.f;
                if (bias) { b0 = bias[c]; b1 = bias[c + 1]; }
                float2 v0 = make_float2(cc[0] + b0, cc[1] + b1);
                float2 v1 = make_float2(cc[2] + b0, cc[3] + b1);
                *(float2*)&C[(size_t)r * ldc + c]       = v0;
                *(float2*)&C[(size_t)(r + 8) * ldc + c] = v1;
            }
        }
}

// ============================================================================
// Scores: P[z] = fp16((Q_h @ K_h^T)/8), pre-split bf16, K=64 single load.
// Block tile 128x128, 8 warps (4M x 2N), warp tile 32x64. ldmatrix fragments.
// Streaming P stores.
// ============================================================================
__global__ __launch_bounds__(256)
void scores_gemm(const __nv_bfloat16* __restrict__ Qh, const __nv_bfloat16* __restrict__ Ql,
                 const __nv_bfloat16* __restrict__ Kh, const __nv_bfloat16* __restrict__ Kl,
                 __half* __restrict__ P)
{
    constexpr int SA = 72;
    __shared__ __align__(16) __nv_bfloat16 AsH[128 * SA];
    __shared__ __align__(16) __nv_bfloat16 AsL[128 * SA];
    __shared__ __align__(16) __nv_bfloat16 BsH[128 * SA];
    __shared__ __align__(16) __nv_bfloat16 BsL[128 * SA];

    const int z = blockIdx.z, b = z >> 4, h = z & 15;
    const size_t qo = (size_t)b * SEQX * D_MODELX + h * D_HEADX;
    Qh += qo; Ql += qo; Kh += qo; Kl += qo;
    P += (size_t)z * SEQX * SEQX;

    const int tid  = threadIdx.x;
    const int m0   = blockIdx.y * 128;
    const int n0   = blockIdx.x * 128;
    const int warp = tid >> 5, lane = tid & 31;
    const int wm = (warp & 3) * 32;
    const int wn = (warp >> 2) * 64;
    const int gr = lane >> 2;
    const int gc = lane & 3;
    const int ti = lane >> 3, ri = lane & 7;

    #pragma unroll
    for (int i = 0; i < 4; i++) {
        int idx = tid + i * 256, row = idx >> 3, c8 = idx & 7;
        size_t oa = (size_t)(m0 + row) * D_MODELX + c8 * 8;
        size_t ob = (size_t)(n0 + row) * D_MODELX + c8 * 8;
        *(uint4*)&AsH[row * SA + c8 * 8] = *(const uint4*)(Qh + oa);
        *(uint4*)&AsL[row * SA + c8 * 8] = *(const uint4*)(Ql + oa);
        *(uint4*)&BsH[row * SA + c8 * 8] = *(const uint4*)(Kh + ob);
        *(uint4*)&BsL[row * SA + c8 * 8] = *(const uint4*)(Kl + ob);
    }
    __syncthreads();

    unsigned aHb[2], aLb[2], bHb[4], bLb[4];
    #pragma unroll
    for (int mi = 0; mi < 2; mi++) {
        int row = wm + mi * 16 + (ti & 1) * 8 + ri;
        int col = (ti >> 1) * 8;
        aHb[mi] = smem_u32(&AsH[row * SA + col]);
        aLb[mi] = smem_u32(&AsL[row * SA + col]);
    }
    #pragma unroll
    for (int nip = 0; nip < 4; nip++) {
        int row = wn + (nip * 2 + (ti >> 1)) * 8 + ri;
        int col = (ti & 1) * 8;
        bHb[nip] = smem_u32(&BsH[row * SA + col]);
        bLb[nip] = smem_u32(&BsL[row * SA + col]);
    }

    float acc[2][8][4] = {};

    #pragma unroll
    for (int ks = 0; ks < 4; ks++) {
        const int kb2 = ks * 32;
        unsigned aH[2][4], aL[2][4], bH[4][4], bL[4][4];
        #pragma unroll
        for (int mi = 0; mi < 2; mi++) {
            LDSM_X4(aH[mi][0], aH[mi][1], aH[mi][2], aH[mi][3], aHb[mi] + kb2);
            LDSM_X4(aL[mi][0], aL[mi][1], aL[mi][2], aL[mi][3], aLb[mi] + kb2);
        }
        #pragma unroll
        for (int nip = 0; nip < 4; nip++) {
            LDSM_X4(bH[nip][0], bH[nip][1], bH[nip][2], bH[nip][3], bHb[nip] + kb2);
            LDSM_X4(bL[nip][0], bL[nip][1], bL[nip][2], bL[nip][3], bLb[nip] + kb2);
        }
        #pragma unroll
        for (int nip = 0; nip < 4; nip++)
            #pragma unroll
            for (int hh = 0; hh < 2; hh++) {
                int ni = nip * 2 + hh;
                unsigned b0 = bH[nip][hh * 2], b1 = bH[nip][hh * 2 + 1];
                unsigned l0 = bL[nip][hh * 2], l1 = bL[nip][hh * 2 + 1];
                #pragma unroll
                for (int mi = 0; mi < 2; mi++) {
                    MMA_BF16(acc[mi][ni], aH[mi][0], aH[mi][1], aH[mi][2], aH[mi][3], b0, b1);
                    MMA_BF16(acc[mi][ni], aH[mi][0], aH[mi][1], aH[mi][2], aH[mi][3], l0, l1);
                    MMA_BF16(acc[mi][ni], aL[mi][0], aL[mi][1], aL[mi][2], aL[mi][3], b0, b1);
                }
            }
    }

    #pragma unroll
    for (int mi = 0; mi < 2; mi++)
        #pragma unroll
        for (int ni = 0; ni < 8; ni++) {
            int r = m0 + wm + mi * 16 + gr;
            int c = n0 + wn + ni * 8 + gc * 2;
            float* cc = acc[mi][ni];
            __half2 h0 = __floats2half2_rn(cc[0] * 0.125f, cc[1] * 0.125f);
            __half2 h1 = __floats2half2_rn(cc[2] * 0.125f, cc[3] * 0.125f);
            __stcs((int*)&P[(size_t)r * SEQX + c], *(int*)&h0);
            __stcs((int*)&P[(size_t)(r + 8) * SEQX + c], *(int*)&h1);
        }
}

// ============================================================================
// stats + head-average (no P rewrite). One uint4 streaming load per thread
// per head; dual reduction arrays (2 barriers/head).
// ============================================================================
__global__ __launch_bounds__(256)
void stats_avg_kernel(const __half* __restrict__ P, float* __restrict__ avg,
                      float* __restrict__ rmax, float* __restrict__ rinv)
{
    __shared__ float redm[8], reds[8];
    const int bq = blockIdx.x;
    const int t  = threadIdx.x;
    const int b  = bq >> 11;
    const int q  = bq & 2047;

    float avgacc[8] = {};

    for (int h = 0; h < NUM_HEADSX; ++h) {
        const int z = b * 16 + h;
        const uint4* p4 = (const uint4*)(P + ((size_t)z * SEQX + q) * SEQX);
        uint4 u = __ldcs(p4 + t);   // 8 contiguous halfs: cols t*8 .. t*8+7

        float2 v[4];
        v[0] = __half22float2(*reinterpret_cast<__half2*>(&u.x));
        v[1] = __half22float2(*reinterpret_cast<__half2*>(&u.y));
        v[2] = __half22float2(*reinterpret_cast<__half2*>(&u.z));
        v[3] = __half22float2(*reinterpret_cast<__half2*>(&u.w));

        float mx = -1e30f;
        #pragma unroll
        for (int i = 0; i < 4; i++)
            mx = fmaxf(mx, fmaxf(v[i].x, v[i].y));
        #pragma unroll
        for (int o = 16; o > 0; o >>= 1)
            mx = fmaxf(mx, __shfl_xor_sync(0xffffffffu, mx, o));
        if ((t & 31) == 0) redm[t >> 5] = mx;
        __syncthreads();
        float bm = redm[0];
        #pragma unroll
        for (int w = 1; w < 8; w++) bm = fmaxf(bm, redm[w]);

        float s = 0.f;
        #pragma unroll
        for (int i = 0; i < 4; i++) {
            v[i].x = __expf(v[i].x - bm);
            v[i].y = __expf(v[i].y - bm);
            s += v[i].x + v[i].y;
        }
        #pragma unroll
        for (int o = 16; o > 0; o >>= 1)
            s += __shfl_xor_sync(0xffffffffu, s, o);
        if ((t & 31) == 0) reds[t >> 5] = s;
        __syncthreads();
        float bs = 0.f;
        #pragma unroll
        for (int w = 0; w < 8; w++) bs += reds[w];
        float inv = 1.0f / bs;
        if (t == 0) {
            rmax[(size_t)z * SEQX + q] = bm;
            rinv[(size_t)z * SEQX + q] = inv;
        }

        #pragma unroll
        for (int i = 0; i < 4; i++) {
            avgacc[2 * i]     += v[i].x * inv;
            avgacc[2 * i + 1] += v[i].y * inv;
        }
    }

    float* a = avg + (size_t)bq * SEQX + t * 8;
    float4 o0 = make_float4(avgacc[0] * (1.0f / NUM_HEADSX),
                            avgacc[1] * (1.0f / NUM_HEADSX),
                            avgacc[2] * (1.0f / NUM_HEADSX),
                            avgacc[3] * (1.0f / NUM_HEADSX));
    float4 o1 = make_float4(avgacc[4] * (1.0f / NUM_HEADSX),
                            avgacc[5] * (1.0f / NUM_HEADSX),
                            avgacc[6] * (1.0f / NUM_HEADSX),
                            avgacc[7] * (1.0f / NUM_HEADSX));
    __stcs((float4*)a, o0);
    __stcs((float4*)(a + 4), o1);
}

// ============================================================================
// AV: O_h = softmax(P)[z] @ Vt_h^T, exp on load, fp16 hi/lo V, ldmatrix frags.
// Streaming P loads.
// ============================================================================
__global__ __launch_bounds__(256)
void av_gemm(const __half* __restrict__ P,
             const __half* __restrict__ Vh, const __half* __restrict__ Vl,
             const float* __restrict__ rmax, const float* __restrict__ rinv,
             float* __restrict__ O)
{
    constexpr int BM = 128, BK = 64;
    constexpr int SA = 72;

    __shared__ __align__(16) __half As[BM * SA];
    __shared__ __align__(16) __half BsH[64 * SA];
    __shared__ __align__(16) __half BsL[64 * SA];
    __shared__ float sm_m[BM], sm_i[BM];

    const int z = blockIdx.z, b = z >> 4, h = z & 15;
    P  += (size_t)z * SEQX * SEQX;
    Vh += (size_t)z * D_HEADX * SEQX;
    Vl += (size_t)z * D_HEADX * SEQX;
    O  += (size_t)b * SEQX * D_MODELX + h * D_HEADX;
    rmax += (size_t)z * SEQX;
    rinv += (size_t)z * SEQX;

    const int tid  = threadIdx.x;
    const int m0   = blockIdx.y * BM;
    const int warp = tid >> 5, lane = tid & 31;
    const int wm = (warp & 3) * 32;
    const int wn = (warp >> 2) * 32;
    const int gr = lane >> 2;
    const int gc = lane & 3;
    const int ti = lane >> 3, ri = lane & 7;

    if (tid < BM) { sm_m[tid] = rmax[m0 + tid]; sm_i[tid] = rinv[m0 + tid]; }
    __syncthreads();

    unsigned ab[2], bHb[2], bLb[2];
    #pragma unroll
    for (int mi = 0; mi < 2; mi++) {
        int row = wm + mi * 16 + (ti & 1) * 8 + ri;
        int col = (ti >> 1) * 8;
        ab[mi] = smem_u32(&As[row * SA + col]);
    }
    #pragma unroll
    for (int nip = 0; nip < 2; nip++) {
        int row = wn + (nip * 2 + (ti >> 1)) * 8 + ri;
        int col = (ti & 1) * 8;
        bHb[nip] = smem_u32(&BsH[row * SA + col]);
        bLb[nip] = smem_u32(&BsL[row * SA + col]);
    }

    float acc[2][4][4] = {};
    uint4 pa[4], pbh[2], pbl[2];

    {
        #pragma unroll
        for (int i = 0; i < 4; i++) {
            int idx = tid + i * 256, row = idx >> 3, c8 = idx & 7;
            pa[i] = __ldcs((const uint4*)(P + (size_t)(m0 + row) * SEQX + c8 * 8));
        }
        #pragma unroll
        for (int i = 0; i < 2; i++) {
            int idx = tid + i * 256, row = idx >> 3, c8 = idx & 7;
            pbh[i] = *(const uint4*)(Vh + (size_t)row * SEQX + c8 * 8);
            pbl[i] = *(const uint4*)(Vl + (size_t)row * SEQX + c8 * 8);
        }
    }

    const int niter = SEQX / BK;  // 32
    for (int it = 0; it < niter; ++it) {
        #pragma unroll
        for (int i = 0; i < 4; i++) {
            int idx = tid + i * 256, row = idx >> 3, c8 = idx & 7;
            float m = sm_m[row], inv = sm_i[row];
            const __half2* hp = (const __half2*)&pa[i];
            uint4 out;
            unsigned* op = (unsigned*)&out;
            #pragma unroll
            for (int j = 0; j < 4; j++) {
                float2 f = __half22float2(hp[j]);
                __half2 e = __floats2half2_rn(__expf(f.x - m) * inv,
                                              __expf(f.y - m) * inv);
                op[j] = *(unsigned*)&e;
            }
            *(uint4*)&As[row * SA + c8 * 8] = out;
        }
        #pragma unroll
        for (int i = 0; i < 2; i++) {
            int idx = tid + i * 256, row = idx >> 3, c8 = idx & 7;
            *(uint4*)&BsH[row * SA + c8 * 8] = pbh[i];
            *(uint4*)&BsL[row * SA + c8 * 8] = pbl[i];
        }
        __syncthreads();

        if (it + 1 < niter) {
            int k0 = (it + 1) * BK;
            #pragma unroll
            for (int i = 0; i < 4; i++) {
                int idx = tid + i * 256, row = idx >> 3, c8 = idx & 7;
                pa[i] = __ldcs((const uint4*)(P + (size_t)(m0 + row) * SEQX + k0 + c8 * 8));
            }
            #pragma unroll
            for (int i = 0; i < 2; i++) {
                int idx = tid + i * 256, row = idx >> 3, c8 = idx & 7;
                pbh[i] = *(const uint4*)(Vh + (size_t)row * SEQX + k0 + c8 * 8);
                pbl[i] = *(const uint4*)(Vl + (size_t)row * SEQX + k0 + c8 * 8);
            }
        }

        #pragma unroll
        for (int ks = 0; ks < 4; ks++) {
            const int kb2 = ks * 32;
            unsigned a[2][4], bH[2][4], bL[2][4];
            #pragma unroll
            for (int mi = 0; mi < 2; mi++)
                LDSM_X4(a[mi][0], a[mi][1], a[mi][2], a[mi][3], ab[mi] + kb2);
            #pragma unroll
            for (int nip = 0; nip < 2; nip++) {
                LDSM_X4(bH[nip][0], bH[nip][1], bH[nip][2], bH[nip][3], bHb[nip] + kb2);
                LDSM_X4(bL[nip][0], bL[nip][1], bL[nip][2], bL[nip][3], bLb[nip] + kb2);
            }
            #pragma unroll
            for (int mi = 0; mi < 2; mi++)
                #pragma unroll
                for (int nip = 0; nip < 2; nip++)
                    #pragma unroll
                    for (int hh = 0; hh < 2; hh++) {
                        int ni = nip * 2 + hh;
                        MMA_F16(acc[mi][ni], a[mi][0], a[mi][1], a[mi][2], a[mi][3],
                                bH[nip][hh * 2], bH[nip][hh * 2 + 1]);
                        MMA_F16(acc[mi][ni], a[mi][0], a[mi][1], a[mi][2], a[mi][3],
                                bL[nip][hh * 2], bL[nip][hh * 2 + 1]);
                    }
        }
        __syncthreads();
    }

    #pragma unroll
    for (int mi = 0; mi < 2; mi++)
        #pragma unroll
        for (int ni = 0; ni < 4; ni++) {
            int r = m0 + wm + mi * 16 + gr;
            int c = wn + ni * 8 + gc * 2;
            float* cc = acc[mi][ni];
            *(float2*)&O[(size_t)r * D_MODELX + c]       = make_float2(cc[0], cc[1]);
            *(float2*)&O[(size_t)(r + 8) * D_MODELX + c] = make_float2(cc[2], cc[3]);
        }
}

// ============================================================================
// launch
// ============================================================================
extern "C" void kernel_launch(void* const* d_in, const int* in_sizes, int n_in,
                              void* d_out, int out_size)
{
    const float* x_q = (const float*)d_in[0];
    const float* x_k = (const float*)d_in[1];
    const float* x_v = (const float*)d_in[2];
    const float* Wq  = (const float*)d_in[3];
    const float* bq  = (const float*)d_in[4];
    const float* Wk  = (const float*)d_in[5];
    const float* bk  = (const float*)d_in[6];
    const float* Wv  = (const float*)d_in[7];
    const float* bv  = (const float*)d_in[8];
    const float* Wo  = (const float*)d_in[9];
    const float* bo  = (const float*)d_in[10];

    float* out = (float*)d_out;
    float* avg = out + (size_t)M_TOK * D_MODELX;

    __nv_bfloat16 *Qh, *Ql, *Kh, *Kl;
    __half *Vth, *Vtl, *P;
    float *gO, *rmax, *rinv;
    cudaGetSymbolAddress((void**)&Qh, g_Qh);
    cudaGetSymbolAddress((void**)&Ql, g_Ql);
    cudaGetSymbolAddress((void**)&Kh, g_Kh);
    cudaGetSymbolAddress((void**)&Kl, g_Kl);
    cudaGetSymbolAddress((void**)&Vth, g_Vth);
    cudaGetSymbolAddress((void**)&Vtl, g_Vtl);
    cudaGetSymbolAddress((void**)&gO, g_O);
    cudaGetSymbolAddress((void**)&P, g_P);
    cudaGetSymbolAddress((void**)&rmax, g_rmax);
    cudaGetSymbolAddress((void**)&rinv, g_rinv);

    dim3 blk(256);
    dim3 gproj(D_MODELX / 64, M_TOK / 128, 1);   // (16, 64)

    // 1-3) projections: Q/K -> bf16 hi/lo, V -> transposed fp16 hi/lo
    mma_gemm<5><<<gproj, blk>>>(x_q, Wq, nullptr, Qh, Ql,
                                D_MODELX, D_MODELX, D_MODELX, D_MODELX, bq);
    mma_gemm<5><<<gproj, blk>>>(x_k, Wk, nullptr, Kh, Kl,
                                D_MODELX, D_MODELX, D_MODELX, D_MODELX, bk);
    mma_gemm<3><<<gproj, blk>>>(x_v, Wv, nullptr, Vth, Vtl,
                                D_MODELX, D_MODELX, 0, D_MODELX, bv);

    // 4) scores: raw fp16 P = (Q_h @ K_h^T) / 8
    dim3 gsc(SEQX / 128, SEQX / 128, NZ);        // (16, 16, 64)
    scores_gemm<<<gsc, blk>>>(Qh, Ql, Kh, Kl, P);

    // 5) softmax stats + head-average (no P rewrite)
    stats_avg_kernel<<<M_TOK, blk>>>(P, avg, rmax, rinv);

    // 6) AV fp16 MMA with on-the-fly exp
    dim3 gav(1, SEQX / 128, NZ);                 // (1, 16, 64)
    av_gemm<<<gav, blk>>>(P, Vth, Vtl, rmax, rinv, gO);

    // 7) output projection (fp32 out)
    mma_gemm<0><<<gproj, blk>>>(gO, Wo, out, nullptr, nullptr,
                                D_MODELX, D_MODELX, D_MODELX, D_MODELX, bo);
}

// round 11
// speedup vs baseline: 1.1234x; 1.0072x over previous
#include <cuda_runtime.h>
#include <cuda_bf16.h>
#include <cuda_fp16.h>
#include <cstdint>

#define D_MODELX 1024
#define NUM_HEADSX 16
#define D_HEADX 64
#define BATCHX 4
#define SEQX 2048
#define M_TOK (BATCHX * SEQX)    // 8192
#define NZ (BATCHX * NUM_HEADSX) // 64

// ---- static device scratch ----
__device__ __nv_bfloat16 g_Qh[(size_t)M_TOK * D_MODELX];
__device__ __nv_bfloat16 g_Ql[(size_t)M_TOK * D_MODELX];
__device__ __nv_bfloat16 g_Kh[(size_t)M_TOK * D_MODELX];
__device__ __nv_bfloat16 g_Kl[(size_t)M_TOK * D_MODELX];
__device__ __half g_Vth[(size_t)M_TOK * D_MODELX];  // [Z][64][2048] fp16 hi
__device__ __half g_Vtl[(size_t)M_TOK * D_MODELX];  // [Z][64][2048] fp16 lo
__device__ float  g_O[(size_t)M_TOK * D_MODELX];
__device__ __half g_P[(size_t)NZ * SEQX * SEQX];    // 0.5 GiB fp16 exp(scores)
__device__ float  g_psum[(size_t)NZ * SEQX * 16];   // per-row partial sums
__device__ float  g_rinv[(size_t)NZ * SEQX];

__device__ __forceinline__ unsigned pack_bf2(float x, float y) {
    __nv_bfloat162 t = __floats2bfloat162_rn(x, y);
    return *reinterpret_cast<unsigned*>(&t);
}

__device__ __forceinline__ unsigned smem_u32(const void* p) {
    return (unsigned)__cvta_generic_to_shared(p);
}

#define LDSM_X4(r0, r1, r2, r3, addr)                                         \
    asm volatile("ldmatrix.sync.aligned.m8n8.x4.shared.b16 {%0,%1,%2,%3}, [%4];" \
        : "=r"(r0), "=r"(r1), "=r"(r2), "=r"(r3) : "r"(addr))

#define MMA_BF16(c, a0, a1, a2, a3, b0, b1)                                   \
    asm volatile(                                                             \
        "mma.sync.aligned.m16n8k16.row.col.f32.bf16.bf16.f32 "                \
        "{%0,%1,%2,%3},{%4,%5,%6,%7},{%8,%9},{%0,%1,%2,%3};"                  \
        : "+f"(c[0]), "+f"(c[1]), "+f"(c[2]), "+f"(c[3])                      \
        : "r"(a0), "r"(a1), "r"(a2), "r"(a3), "r"(b0), "r"(b1))

#define MMA_F16(c, a0, a1, a2, a3, b0, b1)                                    \
    asm volatile(                                                             \
        "mma.sync.aligned.m16n8k16.row.col.f32.f16.f16.f32 "                  \
        "{%0,%1,%2,%3},{%4,%5,%6,%7},{%8,%9},{%0,%1,%2,%3};"                  \
        : "+f"(c[0]), "+f"(c[1]), "+f"(c[2]), "+f"(c[3])                      \
        : "r"(a0), "r"(a1), "r"(a2), "r"(a3), "r"(b0), "r"(b1))

// ============================================================================
// NT bf16-split MMA GEMM (fp32 in, split in-kernel): C = A @ B^T + bias
// MODE 0: fp32 out + bias (output projection)
// MODE 3: V projection, transposed fp16 hi/lo store into [Z][64][2048]
// MODE 5: Q/K projection, bf16 hi/lo out + bias
// Block tile 128x64x32, 256 threads (8 warps 4x2), warp tile 32x32, ldmatrix.
// ============================================================================
template <int MODE>
__global__ __launch_bounds__(256)
void mma_gemm(const float* __restrict__ A,
              const float* __restrict__ B,
              float* __restrict__ C,
              void* __restrict__ Chv, void* __restrict__ Clv,
              int lda, int ldb, int ldc,
              int K, const float* __restrict__ bias)
{
    constexpr int BM = 128, BN = 64, BK = 32;
    constexpr int SA = 40;

    __shared__ __align__(16) __nv_bfloat16 AsH[BM * SA];
    __shared__ __align__(16) __nv_bfloat16 AsL[BM * SA];
    __shared__ __align__(16) __nv_bfloat16 BsH[BN * SA];
    __shared__ __align__(16) __nv_bfloat16 BsL[BN * SA];

    const int tid  = threadIdx.x;
    const int m0   = blockIdx.y * BM;
    const int n0   = blockIdx.x * BN;
    const int warp = tid >> 5, lane = tid & 31;
    const int wm = (warp & 3) * 32;
    const int wn = (warp >> 2) * 32;
    const int gr = lane >> 2;
    const int gc = lane & 3;
    const int ti = lane >> 3, ri = lane & 7;

    unsigned aHb[2], aLb[2], bHb[2], bLb[2];
    #pragma unroll
    for (int mi = 0; mi < 2; mi++) {
        int row = wm + mi * 16 + (ti & 1) * 8 + ri;
        int col = (ti >> 1) * 8;
        aHb[mi] = smem_u32(&AsH[row * SA + col]);
        aLb[mi] = smem_u32(&AsL[row * SA + col]);
    }
    #pragma unroll
    for (int nip = 0; nip < 2; nip++) {
        int row = wn + (nip * 2 + (ti >> 1)) * 8 + ri;
        int col = (ti & 1) * 8;
        bHb[nip] = smem_u32(&BsH[row * SA + col]);
        bLb[nip] = smem_u32(&BsL[row * SA + col]);
    }

    float acc[2][4][4] = {};
    float4 ra[4], rb[2];

    {
        #pragma unroll
        for (int i = 0; i < 4; i++) {
            int idx = tid + i * 256, row = idx >> 3, c4 = idx & 7;
            ra[i] = *(const float4*)(A + (size_t)(m0 + row) * lda + c4 * 4);
        }
        #pragma unroll
        for (int i = 0; i < 2; i++) {
            int idx = tid + i * 256, row = idx >> 3, c4 = idx & 7;
            rb[i] = *(const float4*)(B + (size_t)(n0 + row) * ldb + c4 * 4);
        }
    }

    const int niter = K / BK;
    for (int it = 0; it < niter; ++it) {
        #pragma unroll
        for (int i = 0; i < 4; i++) {
            int idx = tid + i * 256, row = idx >> 3, c4 = idx & 7;
            float v0 = ra[i].x, v1 = ra[i].y, v2 = ra[i].z, v3 = ra[i].w;
            float h0 = __bfloat162float(__float2bfloat16_rn(v0));
            float h1 = __bfloat162float(__float2bfloat16_rn(v1));
            float h2 = __bfloat162float(__float2bfloat16_rn(v2));
            float h3 = __bfloat162float(__float2bfloat16_rn(v3));
            uint2 H, L;
            H.x = pack_bf2(v0, v1); H.y = pack_bf2(v2, v3);
            L.x = pack_bf2(v0 - h0, v1 - h1); L.y = pack_bf2(v2 - h2, v3 - h3);
            *(uint2*)&AsH[row * SA + c4 * 4] = H;
            *(uint2*)&AsL[row * SA + c4 * 4] = L;
        }
        #pragma unroll
        for (int i = 0; i < 2; i++) {
            int idx = tid + i * 256, row = idx >> 3, c4 = idx & 7;
            float v0 = rb[i].x, v1 = rb[i].y, v2 = rb[i].z, v3 = rb[i].w;
            float h0 = __bfloat162float(__float2bfloat16_rn(v0));
            float h1 = __bfloat162float(__float2bfloat16_rn(v1));
            float h2 = __bfloat162float(__float2bfloat16_rn(v2));
            float h3 = __bfloat162float(__float2bfloat16_rn(v3));
            uint2 H, L;
            H.x = pack_bf2(v0, v1); H.y = pack_bf2(v2, v3);
            L.x = pack_bf2(v0 - h0, v1 - h1); L.y = pack_bf2(v2 - h2, v3 - h3);
            *(uint2*)&BsH[row * SA + c4 * 4] = H;
            *(uint2*)&BsL[row * SA + c4 * 4] = L;
        }
        __syncthreads();

        if (it + 1 < niter) {
            int k0 = (it + 1) * BK;
            #pragma unroll
            for (int i = 0; i < 4; i++) {
                int idx = tid + i * 256, row = idx >> 3, c4 = idx & 7;
                ra[i] = *(const float4*)(A + (size_t)(m0 + row) * lda + k0 + c4 * 4);
            }
            #pragma unroll
            for (int i = 0; i < 2; i++) {
                int idx = tid + i * 256, row = idx >> 3, c4 = idx & 7;
                rb[i] = *(const float4*)(B + (size_t)(n0 + row) * ldb + k0 + c4 * 4);
            }
        }

        #pragma unroll
        for (int ks = 0; ks < 2; ks++) {
            const int kb2 = ks * 32;
            unsigned aH[2][4], aL[2][4], bH[2][4], bL[2][4];
            #pragma unroll
            for (int mi = 0; mi < 2; mi++) {
                LDSM_X4(aH[mi][0], aH[mi][1], aH[mi][2], aH[mi][3], aHb[mi] + kb2);
                LDSM_X4(aL[mi][0], aL[mi][1], aL[mi][2], aL[mi][3], aLb[mi] + kb2);
            }
            #pragma unroll
            for (int nip = 0; nip < 2; nip++) {
                LDSM_X4(bH[nip][0], bH[nip][1], bH[nip][2], bH[nip][3], bHb[nip] + kb2);
                LDSM_X4(bL[nip][0], bL[nip][1], bL[nip][2], bL[nip][3], bLb[nip] + kb2);
            }
            #pragma unroll
            for (int mi = 0; mi < 2; mi++)
                #pragma unroll
                for (int nip = 0; nip < 2; nip++)
                    #pragma unroll
                    for (int hh = 0; hh < 2; hh++) {
                        int ni = nip * 2 + hh;
                        unsigned b0 = bH[nip][hh * 2], b1 = bH[nip][hh * 2 + 1];
                        unsigned l0 = bL[nip][hh * 2], l1 = bL[nip][hh * 2 + 1];
                        MMA_BF16(acc[mi][ni], aH[mi][0], aH[mi][1], aH[mi][2], aH[mi][3], b0, b1);
                        MMA_BF16(acc[mi][ni], aH[mi][0], aH[mi][1], aH[mi][2], aH[mi][3], l0, l1);
                        MMA_BF16(acc[mi][ni], aL[mi][0], aL[mi][1], aL[mi][2], aL[mi][3], b0, b1);
                    }
        }
        __syncthreads();
    }

    #pragma unroll
    for (int mi = 0; mi < 2; mi++)
        #pragma unroll
        for (int ni = 0; ni < 4; ni++) {
            int r = m0 + wm + mi * 16 + gr;
            int c = n0 + wn + ni * 8 + gc * 2;
            float* cc = acc[mi][ni];
            if (MODE == 3) {
                __half* Ch = (__half*)Chv;
                __half* Cl = (__half*)Clv;
                int b = r >> 11, s = r & 2047;
                int h = c >> 6, d = c & 63;
                float b0 = bias[c], b1 = bias[c + 1];
                float v00 = cc[0] + b0, v01 = cc[1] + b1;
                float v10 = cc[2] + b0, v11 = cc[3] + b1;
                size_t base = ((size_t)(b * 16 + h) * 64 + d) * 2048;
                __half h00 = __float2half_rn(v00);
                __half h01 = __float2half_rn(v01);
                __half h10 = __float2half_rn(v10);
                __half h11 = __float2half_rn(v11);
                Ch[base + s]            = h00;
                Ch[base + 2048 + s]     = h01;
                Ch[base + s + 8]        = h10;
                Ch[base + 2048 + s + 8] = h11;
                Cl[base + s]            = __float2half_rn(v00 - __half2float(h00));
                Cl[base + 2048 + s]     = __float2half_rn(v01 - __half2float(h01));
                Cl[base + s + 8]        = __float2half_rn(v10 - __half2float(h10));
                Cl[base + 2048 + s + 8] = __float2half_rn(v11 - __half2float(h11));
            } else if (MODE == 5) {
                __nv_bfloat16* Ch = (__nv_bfloat16*)Chv;
                __nv_bfloat16* Cl = (__nv_bfloat16*)Clv;
                float b0 = bias[c], b1 = bias[c + 1];
                float v00 = cc[0] + b0, v01 = cc[1] + b1;
                float v10 = cc[2] + b0, v11 = cc[3] + b1;
                float h00 = __bfloat162float(__float2bfloat16_rn(v00));
                float h01 = __bfloat162float(__float2bfloat16_rn(v01));
                float h10 = __bfloat162float(__float2bfloat16_rn(v10));
                float h11 = __bfloat162float(__float2bfloat16_rn(v11));
                size_t o0 = (size_t)r * ldc + c;
                size_t o1 = (size_t)(r + 8) * ldc + c;
                *(unsigned*)&Ch[o0] = pack_bf2(v00, v01);
                *(unsigned*)&Ch[o1] = pack_bf2(v10, v11);
                *(unsigned*)&Cl[o0] = pack_bf2(v00 - h00, v01 - h01);
                *(unsigned*)&Cl[o1] = pack_bf2(v10 - h10, v11 - h11);
            } else {
                float b0 = 0.f, b1 = 0.f;
                if (bias) { b0 = bias[c]; b1 = bias[c + 1]; }
                float2 v0 = make_float2(cc[0] + b0, cc[1] + b1);
                float2 v1 = make_float2(cc[2] + b0, cc[3] + b1);
                *(float2*)&C[(size_t)r * ldc + c]       = v0;
                *(float2*)&C[(size_t)(r + 8) * ldc + c] = v1;
            }
        }
}

// ============================================================================
// Scores: P[z] = fp16(exp((Q_h @ K_h^T)/8)), pre-split bf16, K=64 single load.
// Epilogue computes exp + per-row partial sums into g_psum (deterministic).
// Block tile 128x128, 8 warps (4M x 2N), warp tile 32x64. ldmatrix fragments.
// ============================================================================
__global__ __launch_bounds__(256)
void scores_gemm(const __nv_bfloat16* __restrict__ Qh, const __nv_bfloat16* __restrict__ Ql,
                 const __nv_bfloat16* __restrict__ Kh, const __nv_bfloat16* __restrict__ Kl,
                 __half* __restrict__ P, float* __restrict__ PS)
{
    constexpr int SA = 72;
    __shared__ __align__(16) __nv_bfloat16 AsH[128 * SA];
    __shared__ __align__(16) __nv_bfloat16 AsL[128 * SA];
    __shared__ __align__(16) __nv_bfloat16 BsH[128 * SA];
    __shared__ __align__(16) __nv_bfloat16 BsL[128 * SA];
    __shared__ float psum[2][128];

    const int z = blockIdx.z, b = z >> 4, h = z & 15;
    const size_t qo = (size_t)b * SEQX * D_MODELX + h * D_HEADX;
    Qh += qo; Ql += qo; Kh += qo; Kl += qo;
    P += (size_t)z * SEQX * SEQX;

    const int tid  = threadIdx.x;
    const int m0   = blockIdx.y * 128;
    const int n0   = blockIdx.x * 128;
    const int warp = tid >> 5, lane = tid & 31;
    const int wm = (warp & 3) * 32;
    const int wn = (warp >> 2) * 64;
    const int gr = lane >> 2;
    const int gc = lane & 3;
    const int ti = lane >> 3, ri = lane & 7;

    #pragma unroll
    for (int i = 0; i < 4; i++) {
        int idx = tid + i * 256, row = idx >> 3, c8 = idx & 7;
        size_t oa = (size_t)(m0 + row) * D_MODELX + c8 * 8;
        size_t ob = (size_t)(n0 + row) * D_MODELX + c8 * 8;
        *(uint4*)&AsH[row * SA + c8 * 8] = *(const uint4*)(Qh + oa);
        *(uint4*)&AsL[row * SA + c8 * 8] = *(const uint4*)(Ql + oa);
        *(uint4*)&BsH[row * SA + c8 * 8] = *(const uint4*)(Kh + ob);
        *(uint4*)&BsL[row * SA + c8 * 8] = *(const uint4*)(Kl + ob);
    }
    __syncthreads();

    unsigned aHb[2], aLb[2], bHb[4], bLb[4];
    #pragma unroll
    for (int mi = 0; mi < 2; mi++) {
        int row = wm + mi * 16 + (ti & 1) * 8 + ri;
        int col = (ti >> 1) * 8;
        aHb[mi] = smem_u32(&AsH[row * SA + col]);
        aLb[mi] = smem_u32(&AsL[row * SA + col]);
    }
    #pragma unroll
    for (int nip = 0; nip < 4; nip++) {
        int row = wn + (nip * 2 + (ti >> 1)) * 8 + ri;
        int col = (ti & 1) * 8;
        bHb[nip] = smem_u32(&BsH[row * SA + col]);
        bLb[nip] = smem_u32(&BsL[row * SA + col]);
    }

    float acc[2][8][4] = {};

    #pragma unroll
    for (int ks = 0; ks < 4; ks++) {
        const int kb2 = ks * 32;
        unsigned aH[2][4], aL[2][4], bH[4][4], bL[4][4];
        #pragma unroll
        for (int mi = 0; mi < 2; mi++) {
            LDSM_X4(aH[mi][0], aH[mi][1], aH[mi][2], aH[mi][3], aHb[mi] + kb2);
            LDSM_X4(aL[mi][0], aL[mi][1], aL[mi][2], aL[mi][3], aLb[mi] + kb2);
        }
        #pragma unroll
        for (int nip = 0; nip < 4; nip++) {
            LDSM_X4(bH[nip][0], bH[nip][1], bH[nip][2], bH[nip][3], bHb[nip] + kb2);
            LDSM_X4(bL[nip][0], bL[nip][1], bL[nip][2], bL[nip][3], bLb[nip] + kb2);
        }
        #pragma unroll
        for (int nip = 0; nip < 4; nip++)
            #pragma unroll
            for (int hh = 0; hh < 2; hh++) {
                int ni = nip * 2 + hh;
                unsigned b0 = bH[nip][hh * 2], b1 = bH[nip][hh * 2 + 1];
                unsigned l0 = bL[nip][hh * 2], l1 = bL[nip][hh * 2 + 1];
                #pragma unroll
                for (int mi = 0; mi < 2; mi++) {
                    MMA_BF16(acc[mi][ni], aH[mi][0], aH[mi][1], aH[mi][2], aH[mi][3], b0, b1);
                    MMA_BF16(acc[mi][ni], aH[mi][0], aH[mi][1], aH[mi][2], aH[mi][3], l0, l1);
                    MMA_BF16(acc[mi][ni], aL[mi][0], aL[mi][1], aL[mi][2], aL[mi][3], b0, b1);
                }
            }
    }

    // ---- epilogue: exp, fp16 store, per-row partial sums ----
    float rowsum[4] = {0.f, 0.f, 0.f, 0.f};
    #pragma unroll
    for (int mi = 0; mi < 2; mi++)
        #pragma unroll
        for (int ni = 0; ni < 8; ni++) {
            int r = m0 + wm + mi * 16 + gr;
            int c = n0 + wn + ni * 8 + gc * 2;
            float* cc = acc[mi][ni];
            float e0 = __expf(cc[0] * 0.125f);
            float e1 = __expf(cc[1] * 0.125f);
            float e2 = __expf(cc[2] * 0.125f);
            float e3 = __expf(cc[3] * 0.125f);
            __half2 h0 = __floats2half2_rn(e0, e1);
            __half2 h1 = __floats2half2_rn(e2, e3);
            __stcs((int*)&P[(size_t)r * SEQX + c], *(int*)&h0);
            __stcs((int*)&P[(size_t)(r + 8) * SEQX + c], *(int*)&h1);
            rowsum[mi * 2]     += e0 + e1;
            rowsum[mi * 2 + 1] += e2 + e3;
        }
    #pragma unroll
    for (int j = 0; j < 4; j++) {
        rowsum[j] += __shfl_xor_sync(0xffffffffu, rowsum[j], 1);
        rowsum[j] += __shfl_xor_sync(0xffffffffu, rowsum[j], 2);
    }
    const int wnh = warp >> 2;
    if (gc == 0) {
        psum[wnh][wm + gr]      = rowsum[0];
        psum[wnh][wm + 8 + gr]  = rowsum[1];
        psum[wnh][wm + 16 + gr] = rowsum[2];
        psum[wnh][wm + 24 + gr] = rowsum[3];
    }
    __syncthreads();
    if (tid < 128)
        PS[((size_t)z * SEQX + m0 + tid) * 16 + blockIdx.x] =
            psum[0][tid] + psum[1][tid];
}

// ============================================================================
// rinv: per-row 1/sum over the 16 partial sums (contiguous).
// ============================================================================
__global__ __launch_bounds__(256)
void rinv_kernel(const float* __restrict__ PS, float* __restrict__ rinv)
{
    int i = blockIdx.x * 256 + threadIdx.x;  // over NZ*SEQX = 131072 rows
    const float4* p = (const float4*)(PS + (size_t)i * 16);
    float4 a = p[0], b = p[1], c = p[2], d = p[3];
    float s = ((a.x + a.y) + (a.z + a.w)) + ((b.x + b.y) + (b.z + b.w))
            + ((c.x + c.y) + (c.z + c.w)) + ((d.x + d.y) + (d.z + d.w));
    rinv[i] = 1.0f / s;
}

// ============================================================================
// avg: barrier-free head average. P already holds exp(s).
// ============================================================================
__global__ __launch_bounds__(256)
void avg_kernel(const __half* __restrict__ P, const float* __restrict__ rinv,
                float* __restrict__ avg)
{
    const int bq = blockIdx.x;
    const int t  = threadIdx.x;
    const int b  = bq >> 11;
    const int q  = bq & 2047;

    float acc[8] = {};

    #pragma unroll 4
    for (int h = 0; h < NUM_HEADSX; ++h) {
        const int z = b * 16 + h;
        float inv = rinv[(size_t)z * SEQX + q];
        const uint4* p4 = (const uint4*)(P + ((size_t)z * SEQX + q) * SEQX);
        uint4 u = __ldcs(p4 + t);
        float2 v0 = __half22float2(*reinterpret_cast<__half2*>(&u.x));
        float2 v1 = __half22float2(*reinterpret_cast<__half2*>(&u.y));
        float2 v2 = __half22float2(*reinterpret_cast<__half2*>(&u.z));
        float2 v3 = __half22float2(*reinterpret_cast<__half2*>(&u.w));
        acc[0] += v0.x * inv; acc[1] += v0.y * inv;
        acc[2] += v1.x * inv; acc[3] += v1.y * inv;
        acc[4] += v2.x * inv; acc[5] += v2.y * inv;
        acc[6] += v3.x * inv; acc[7] += v3.y * inv;
    }

    float* a = avg + (size_t)bq * SEQX + t * 8;
    float4 o0 = make_float4(acc[0] * (1.0f / NUM_HEADSX), acc[1] * (1.0f / NUM_HEADSX),
                            acc[2] * (1.0f / NUM_HEADSX), acc[3] * (1.0f / NUM_HEADSX));
    float4 o1 = make_float4(acc[4] * (1.0f / NUM_HEADSX), acc[5] * (1.0f / NUM_HEADSX),
                            acc[6] * (1.0f / NUM_HEADSX), acc[7] * (1.0f / NUM_HEADSX));
    __stcs((float4*)a, o0);
    __stcs((float4*)(a + 4), o1);
}

// ============================================================================
// AV: O_h = (P*rinv)[z] @ Vt_h^T. P holds exp(s); staging multiplies by rinv.
// ============================================================================
__global__ __launch_bounds__(256)
void av_gemm(const __half* __restrict__ P,
             const __half* __restrict__ Vh, const __half* __restrict__ Vl,
             const float* __restrict__ rinv,
             float* __restrict__ O)
{
    constexpr int BM = 128, BK = 64;
    constexpr int SA = 72;

    __shared__ __align__(16) __half As[BM * SA];
    __shared__ __align__(16) __half BsH[64 * SA];
    __shared__ __align__(16) __half BsL[64 * SA];
    __shared__ float sm_i[BM];

    const int z = blockIdx.z, b = z >> 4, h = z & 15;
    P  += (size_t)z * SEQX * SEQX;
    Vh += (size_t)z * D_HEADX * SEQX;
    Vl += (size_t)z * D_HEADX * SEQX;
    O  += (size_t)b * SEQX * D_MODELX + h * D_HEADX;
    rinv += (size_t)z * SEQX;

    const int tid  = threadIdx.x;
    const int m0   = blockIdx.y * BM;
    const int warp = tid >> 5, lane = tid & 31;
    const int wm = (warp & 3) * 32;
    const int wn = (warp >> 2) * 32;
    const int gr = lane >> 2;
    const int gc = lane & 3;
    const int ti = lane >> 3, ri = lane & 7;

    if (tid < BM) sm_i[tid] = rinv[m0 + tid];
    __syncthreads();

    unsigned ab[2], bHb[2], bLb[2];
    #pragma unroll
    for (int mi = 0; mi < 2; mi++) {
        int row = wm + mi * 16 + (ti & 1) * 8 + ri;
        int col = (ti >> 1) * 8;
        ab[mi] = smem_u32(&As[row * SA + col]);
    }
    #pragma unroll
    for (int nip = 0; nip < 2; nip++) {
        int row = wn + (nip * 2 + (ti >> 1)) * 8 + ri;
        int col = (ti & 1) * 8;
        bHb[nip] = smem_u32(&BsH[row * SA + col]);
        bLb[nip] = smem_u32(&BsL[row * SA + col]);
    }

    float acc[2][4][4] = {};
    uint4 pa[4], pbh[2], pbl[2];

    {
        #pragma unroll
        for (int i = 0; i < 4; i++) {
            int idx = tid + i * 256, row = idx >> 3, c8 = idx & 7;
            pa[i] = __ldcs((const uint4*)(P + (size_t)(m0 + row) * SEQX + c8 * 8));
        }
        #pragma unroll
        for (int i = 0; i < 2; i++) {
            int idx = tid + i * 256, row = idx >> 3, c8 = idx & 7;
            pbh[i] = *(const uint4*)(Vh + (size_t)row * SEQX + c8 * 8);
            pbl[i] = *(const uint4*)(Vl + (size_t)row * SEQX + c8 * 8);
        }
    }

    const int niter = SEQX / BK;  // 32
    for (int it = 0; it < niter; ++it) {
        #pragma unroll
        for (int i = 0; i < 4; i++) {
            int idx = tid + i * 256, row = idx >> 3, c8 = idx & 7;
            float inv = sm_i[row];
            const __half2* hp = (const __half2*)&pa[i];
            uint4 out;
            unsigned* op = (unsigned*)&out;
            #pragma unroll
            for (int j = 0; j < 4; j++) {
                float2 f = __half22float2(hp[j]);
                __half2 e = __floats2half2_rn(f.x * inv, f.y * inv);
                op[j] = *(unsigned*)&e;
            }
            *(uint4*)&As[row * SA + c8 * 8] = out;
        }
        #pragma unroll
        for (int i = 0; i < 2; i++) {
            int idx = tid + i * 256, row = idx >> 3, c8 = idx & 7;
            *(uint4*)&BsH[row * SA + c8 * 8] = pbh[i];
            *(uint4*)&BsL[row * SA + c8 * 8] = pbl[i];
        }
        __syncthreads();

        if (it + 1 < niter) {
            int k0 = (it + 1) * BK;
            #pragma unroll
            for (int i = 0; i < 4; i++) {
                int idx = tid + i * 256, row = idx >> 3, c8 = idx & 7;
                pa[i] = __ldcs((const uint4*)(P + (size_t)(m0 + row) * SEQX + k0 + c8 * 8));
            }
            #pragma unroll
            for (int i = 0; i < 2; i++) {
                int idx = tid + i * 256, row = idx >> 3, c8 = idx & 7;
                pbh[i] = *(const uint4*)(Vh + (size_t)row * SEQX + k0 + c8 * 8);
                pbl[i] = *(const uint4*)(Vl + (size_t)row * SEQX + k0 + c8 * 8);
            }
        }

        #pragma unroll
        for (int ks = 0; ks < 4; ks++) {
            const int kb2 = ks * 32;
            unsigned a[2][4], bH[2][4], bL[2][4];
            #pragma unroll
            for (int mi = 0; mi < 2; mi++)
                LDSM_X4(a[mi][0], a[mi][1], a[mi][2], a[mi][3], ab[mi] + kb2);
            #pragma unroll
            for (int nip = 0; nip < 2; nip++) {
                LDSM_X4(bH[nip][0], bH[nip][1], bH[nip][2], bH[nip][3], bHb[nip] + kb2);
                LDSM_X4(bL[nip][0], bL[nip][1], bL[nip][2], bL[nip][3], bLb[nip] + kb2);
            }
            #pragma unroll
            for (int mi = 0; mi < 2; mi++)
                #pragma unroll
                for (int nip = 0; nip < 2; nip++)
                    #pragma unroll
                    for (int hh = 0; hh < 2; hh++) {
                        int ni = nip * 2 + hh;
                        MMA_F16(acc[mi][ni], a[mi][0], a[mi][1], a[mi][2], a[mi][3],
                                bH[nip][hh * 2], bH[nip][hh * 2 + 1]);
                        MMA_F16(acc[mi][ni], a[mi][0], a[mi][1], a[mi][2], a[mi][3],
                                bL[nip][hh * 2], bL[nip][hh * 2 + 1]);
                    }
        }
        __syncthreads();
    }

    #pragma unroll
    for (int mi = 0; mi < 2; mi++)
        #pragma unroll
        for (int ni = 0; ni < 4; ni++) {
            int r = m0 + wm + mi * 16 + gr;
            int c = wn + ni * 8 + gc * 2;
            float* cc = acc[mi][ni];
            *(float2*)&O[(size_t)r * D_MODELX + c]       = make_float2(cc[0], cc[1]);
            *(float2*)&O[(size_t)(r + 8) * D_MODELX + c] = make_float2(cc[2], cc[3]);
        }
}

// ============================================================================
// launch
// ============================================================================
extern "C" void kernel_launch(void* const* d_in, const int* in_sizes, int n_in,
                              void* d_out, int out_size)
{
    const float* x_q = (const float*)d_in[0];
    const float* x_k = (const float*)d_in[1];
    const float* x_v = (const float*)d_in[2];
    const float* Wq  = (const float*)d_in[3];
    const float* bq  = (const float*)d_in[4];
    const float* Wk  = (const float*)d_in[5];
    const float* bk  = (const float*)d_in[6];
    const float* Wv  = (const float*)d_in[7];
    const float* bv  = (const float*)d_in[8];
    const float* Wo  = (const float*)d_in[9];
    const float* bo  = (const float*)d_in[10];

    float* out = (float*)d_out;
    float* avg = out + (size_t)M_TOK * D_MODELX;

    __nv_bfloat16 *Qh, *Ql, *Kh, *Kl;
    __half *Vth, *Vtl, *P;
    float *gO, *psum, *rinv;
    cudaGetSymbolAddress((void**)&Qh, g_Qh);
    cudaGetSymbolAddress((void**)&Ql, g_Ql);
    cudaGetSymbolAddress((void**)&Kh, g_Kh);
    cudaGetSymbolAddress((void**)&Kl, g_Kl);
    cudaGetSymbolAddress((void**)&Vth, g_Vth);
    cudaGetSymbolAddress((void**)&Vtl, g_Vtl);
    cudaGetSymbolAddress((void**)&gO, g_O);
    cudaGetSymbolAddress((void**)&P, g_P);
    cudaGetSymbolAddress((void**)&psum, g_psum);
    cudaGetSymbolAddress((void**)&rinv, g_rinv);

    dim3 blk(256);
    dim3 gproj(D_MODELX / 64, M_TOK / 128, 1);   // (16, 64)

    // 1-3) projections: Q/K -> bf16 hi/lo, V -> transposed fp16 hi/lo
    mma_gemm<5><<<gproj, blk>>>(x_q, Wq, nullptr, Qh, Ql,
                                D_MODELX, D_MODELX, D_MODELX, D_MODELX, bq);
    mma_gemm<5><<<gproj, blk>>>(x_k, Wk, nullptr, Kh, Kl,
                                D_MODELX, D_MODELX, D_MODELX, D_MODELX, bk);
    mma_gemm<3><<<gproj, blk>>>(x_v, Wv, nullptr, Vth, Vtl,
                                D_MODELX, D_MODELX, 0, D_MODELX, bv);

    // 4) scores: P = fp16(exp((Q_h @ K_h^T)/8)), partial row sums to psum
    dim3 gsc(SEQX / 128, SEQX / 128, NZ);        // (16, 16, 64)
    scores_gemm<<<gsc, blk>>>(Qh, Ql, Kh, Kl, P, psum);

    // 5a) per-row 1/sum
    rinv_kernel<<<(NZ * SEQX) / 256, blk>>>(psum, rinv);

    // 5b) head-average (barrier-free)
    avg_kernel<<<M_TOK, blk>>>(P, rinv, avg);

    // 6) AV fp16 MMA (x rinv on staging)
    dim3 gav(1, SEQX / 128, NZ);                 // (1, 16, 64)
    av_gemm<<<gav, blk>>>(P, Vth, Vtl, rinv, gO);

    // 7) output projection (fp32 out)
    mma_gemm<0><<<gproj, blk>>>(gO, Wo, out, nullptr, nullptr,
                                D_MODELX, D_MODELX, D_MODELX, D_MODELX, bo);
}

// round 12
// speedup vs baseline: 1.1242x; 1.0007x over previous
#include <cuda_runtime.h>
#include <cuda_bf16.h>
#include <cuda_fp16.h>
#include <cstdint>

#define D_MODELX 1024
#define NUM_HEADSX 16
#define D_HEADX 64
#define BATCHX 4
#define SEQX 2048
#define M_TOK (BATCHX * SEQX)    // 8192
#define NZ (BATCHX * NUM_HEADSX) // 64

// ---- static device scratch ----
__device__ __nv_bfloat16 g_Qh[(size_t)M_TOK * D_MODELX];
__device__ __nv_bfloat16 g_Ql[(size_t)M_TOK * D_MODELX];
__device__ __nv_bfloat16 g_Kh[(size_t)M_TOK * D_MODELX];
__device__ __nv_bfloat16 g_Kl[(size_t)M_TOK * D_MODELX];
__device__ __half g_Vth[(size_t)M_TOK * D_MODELX];  // [Z][64][2048] fp16 hi
__device__ __half g_Vtl[(size_t)M_TOK * D_MODELX];  // [Z][64][2048] fp16 lo
__device__ float  g_O[(size_t)M_TOK * D_MODELX];
__device__ __half g_P[(size_t)NZ * SEQX * SEQX];    // 0.5 GiB fp16 exp(scores)
__device__ float  g_rinv[(size_t)NZ * SEQX];

__device__ __forceinline__ unsigned pack_bf2(float x, float y) {
    __nv_bfloat162 t = __floats2bfloat162_rn(x, y);
    return *reinterpret_cast<unsigned*>(&t);
}

__device__ __forceinline__ unsigned smem_u32(const void* p) {
    return (unsigned)__cvta_generic_to_shared(p);
}

#define LDSM_X4(r0, r1, r2, r3, addr)                                         \
    asm volatile("ldmatrix.sync.aligned.m8n8.x4.shared.b16 {%0,%1,%2,%3}, [%4];" \
        : "=r"(r0), "=r"(r1), "=r"(r2), "=r"(r3) : "r"(addr))

#define MMA_BF16(c, a0, a1, a2, a3, b0, b1)                                   \
    asm volatile(                                                             \
        "mma.sync.aligned.m16n8k16.row.col.f32.bf16.bf16.f32 "                \
        "{%0,%1,%2,%3},{%4,%5,%6,%7},{%8,%9},{%0,%1,%2,%3};"                  \
        : "+f"(c[0]), "+f"(c[1]), "+f"(c[2]), "+f"(c[3])                      \
        : "r"(a0), "r"(a1), "r"(a2), "r"(a3), "r"(b0), "r"(b1))

#define MMA_F16(c, a0, a1, a2, a3, b0, b1)                                    \
    asm volatile(                                                             \
        "mma.sync.aligned.m16n8k16.row.col.f32.f16.f16.f32 "                  \
        "{%0,%1,%2,%3},{%4,%5,%6,%7},{%8,%9},{%0,%1,%2,%3};"                  \
        : "+f"(c[0]), "+f"(c[1]), "+f"(c[2]), "+f"(c[3])                      \
        : "r"(a0), "r"(a1), "r"(a2), "r"(a3), "r"(b0), "r"(b1))

// ============================================================================
// NT bf16-split MMA GEMM (fp32 in, split in-kernel): C = A @ B^T + bias
// MODE 0: fp32 out + bias (output projection)
// MODE 3: V projection, transposed fp16 hi/lo store into [Z][64][2048]
// MODE 5: Q/K projection, bf16 hi/lo out + bias
// ============================================================================
template <int MODE>
__global__ __launch_bounds__(256)
void mma_gemm(const float* __restrict__ A,
              const float* __restrict__ B,
              float* __restrict__ C,
              void* __restrict__ Chv, void* __restrict__ Clv,
              int lda, int ldb, int ldc,
              int K, const float* __restrict__ bias)
{
    constexpr int BM = 128, BN = 64, BK = 32;
    constexpr int SA = 40;

    __shared__ __align__(16) __nv_bfloat16 AsH[BM * SA];
    __shared__ __align__(16) __nv_bfloat16 AsL[BM * SA];
    __shared__ __align__(16) __nv_bfloat16 BsH[BN * SA];
    __shared__ __align__(16) __nv_bfloat16 BsL[BN * SA];

    const int tid  = threadIdx.x;
    const int m0   = blockIdx.y * BM;
    const int n0   = blockIdx.x * BN;
    const int warp = tid >> 5, lane = tid & 31;
    const int wm = (warp & 3) * 32;
    const int wn = (warp >> 2) * 32;
    const int gr = lane >> 2;
    const int gc = lane & 3;
    const int ti = lane >> 3, ri = lane & 7;

    unsigned aHb[2], aLb[2], bHb[2], bLb[2];
    #pragma unroll
    for (int mi = 0; mi < 2; mi++) {
        int row = wm + mi * 16 + (ti & 1) * 8 + ri;
        int col = (ti >> 1) * 8;
        aHb[mi] = smem_u32(&AsH[row * SA + col]);
        aLb[mi] = smem_u32(&AsL[row * SA + col]);
    }
    #pragma unroll
    for (int nip = 0; nip < 2; nip++) {
        int row = wn + (nip * 2 + (ti >> 1)) * 8 + ri;
        int col = (ti & 1) * 8;
        bHb[nip] = smem_u32(&BsH[row * SA + col]);
        bLb[nip] = smem_u32(&BsL[row * SA + col]);
    }

    float acc[2][4][4] = {};
    float4 ra[4], rb[2];

    {
        #pragma unroll
        for (int i = 0; i < 4; i++) {
            int idx = tid + i * 256, row = idx >> 3, c4 = idx & 7;
            ra[i] = *(const float4*)(A + (size_t)(m0 + row) * lda + c4 * 4);
        }
        #pragma unroll
        for (int i = 0; i < 2; i++) {
            int idx = tid + i * 256, row = idx >> 3, c4 = idx & 7;
            rb[i] = *(const float4*)(B + (size_t)(n0 + row) * ldb + c4 * 4);
        }
    }

    const int niter = K / BK;
    for (int it = 0; it < niter; ++it) {
        #pragma unroll
        for (int i = 0; i < 4; i++) {
            int idx = tid + i * 256, row = idx >> 3, c4 = idx & 7;
            float v0 = ra[i].x, v1 = ra[i].y, v2 = ra[i].z, v3 = ra[i].w;
            float h0 = __bfloat162float(__float2bfloat16_rn(v0));
            float h1 = __bfloat162float(__float2bfloat16_rn(v1));
            float h2 = __bfloat162float(__float2bfloat16_rn(v2));
            float h3 = __bfloat162float(__float2bfloat16_rn(v3));
            uint2 H, L;
            H.x = pack_bf2(v0, v1); H.y = pack_bf2(v2, v3);
            L.x = pack_bf2(v0 - h0, v1 - h1); L.y = pack_bf2(v2 - h2, v3 - h3);
            *(uint2*)&AsH[row * SA + c4 * 4] = H;
            *(uint2*)&AsL[row * SA + c4 * 4] = L;
        }
        #pragma unroll
        for (int i = 0; i < 2; i++) {
            int idx = tid + i * 256, row = idx >> 3, c4 = idx & 7;
            float v0 = rb[i].x, v1 = rb[i].y, v2 = rb[i].z, v3 = rb[i].w;
            float h0 = __bfloat162float(__float2bfloat16_rn(v0));
            float h1 = __bfloat162float(__float2bfloat16_rn(v1));
            float h2 = __bfloat162float(__float2bfloat16_rn(v2));
            float h3 = __bfloat162float(__float2bfloat16_rn(v3));
            uint2 H, L;
            H.x = pack_bf2(v0, v1); H.y = pack_bf2(v2, v3);
            L.x = pack_bf2(v0 - h0, v1 - h1); L.y = pack_bf2(v2 - h2, v3 - h3);
            *(uint2*)&BsH[row * SA + c4 * 4] = H;
            *(uint2*)&BsL[row * SA + c4 * 4] = L;
        }
        __syncthreads();

        if (it + 1 < niter) {
            int k0 = (it + 1) * BK;
            #pragma unroll
            for (int i = 0; i < 4; i++) {
                int idx = tid + i * 256, row = idx >> 3, c4 = idx & 7;
                ra[i] = *(const float4*)(A + (size_t)(m0 + row) * lda + k0 + c4 * 4);
            }
            #pragma unroll
            for (int i = 0; i < 2; i++) {
                int idx = tid + i * 256, row = idx >> 3, c4 = idx & 7;
                rb[i] = *(const float4*)(B + (size_t)(n0 + row) * ldb + k0 + c4 * 4);
            }
        }

        #pragma unroll
        for (int ks = 0; ks < 2; ks++) {
            const int kb2 = ks * 32;
            unsigned aH[2][4], aL[2][4], bH[2][4], bL[2][4];
            #pragma unroll
            for (int mi = 0; mi < 2; mi++) {
                LDSM_X4(aH[mi][0], aH[mi][1], aH[mi][2], aH[mi][3], aHb[mi] + kb2);
                LDSM_X4(aL[mi][0], aL[mi][1], aL[mi][2], aL[mi][3], aLb[mi] + kb2);
            }
            #pragma unroll
            for (int nip = 0; nip < 2; nip++) {
                LDSM_X4(bH[nip][0], bH[nip][1], bH[nip][2], bH[nip][3], bHb[nip] + kb2);
                LDSM_X4(bL[nip][0], bL[nip][1], bL[nip][2], bL[nip][3], bLb[nip] + kb2);
            }
            #pragma unroll
            for (int mi = 0; mi < 2; mi++)
                #pragma unroll
                for (int nip = 0; nip < 2; nip++)
                    #pragma unroll
                    for (int hh = 0; hh < 2; hh++) {
                        int ni = nip * 2 + hh;
                        unsigned b0 = bH[nip][hh * 2], b1 = bH[nip][hh * 2 + 1];
                        unsigned l0 = bL[nip][hh * 2], l1 = bL[nip][hh * 2 + 1];
                        MMA_BF16(acc[mi][ni], aH[mi][0], aH[mi][1], aH[mi][2], aH[mi][3], b0, b1);
                        MMA_BF16(acc[mi][ni], aH[mi][0], aH[mi][1], aH[mi][2], aH[mi][3], l0, l1);
                        MMA_BF16(acc[mi][ni], aL[mi][0], aL[mi][1], aL[mi][2], aL[mi][3], b0, b1);
                    }
        }
        __syncthreads();
    }

    #pragma unroll
    for (int mi = 0; mi < 2; mi++)
        #pragma unroll
        for (int ni = 0; ni < 4; ni++) {
            int r = m0 + wm + mi * 16 + gr;
            int c = n0 + wn + ni * 8 + gc * 2;
            float* cc = acc[mi][ni];
            if (MODE == 3) {
                __half* Ch = (__half*)Chv;
                __half* Cl = (__half*)Clv;
                int b = r >> 11, s = r & 2047;
                int h = c >> 6, d = c & 63;
                float b0 = bias[c], b1 = bias[c + 1];
                float v00 = cc[0] + b0, v01 = cc[1] + b1;
                float v10 = cc[2] + b0, v11 = cc[3] + b1;
                size_t base = ((size_t)(b * 16 + h) * 64 + d) * 2048;
                __half h00 = __float2half_rn(v00);
                __half h01 = __float2half_rn(v01);
                __half h10 = __float2half_rn(v10);
                __half h11 = __float2half_rn(v11);
                Ch[base + s]            = h00;
                Ch[base + 2048 + s]     = h01;
                Ch[base + s + 8]        = h10;
                Ch[base + 2048 + s + 8] = h11;
                Cl[base + s]            = __float2half_rn(v00 - __half2float(h00));
                Cl[base + 2048 + s]     = __float2half_rn(v01 - __half2float(h01));
                Cl[base + s + 8]        = __float2half_rn(v10 - __half2float(h10));
                Cl[base + 2048 + s + 8] = __float2half_rn(v11 - __half2float(h11));
            } else if (MODE == 5) {
                __nv_bfloat16* Ch = (__nv_bfloat16*)Chv;
                __nv_bfloat16* Cl = (__nv_bfloat16*)Clv;
                float b0 = bias[c], b1 = bias[c + 1];
                float v00 = cc[0] + b0, v01 = cc[1] + b1;
                float v10 = cc[2] + b0, v11 = cc[3] + b1;
                float h00 = __bfloat162float(__float2bfloat16_rn(v00));
                float h01 = __bfloat162float(__float2bfloat16_rn(v01));
                float h10 = __bfloat162float(__float2bfloat16_rn(v10));
                float h11 = __bfloat162float(__float2bfloat16_rn(v11));
                size_t o0 = (size_t)r * ldc + c;
                size_t o1 = (size_t)(r + 8) * ldc + c;
                *(unsigned*)&Ch[o0] = pack_bf2(v00, v01);
                *(unsigned*)&Ch[o1] = pack_bf2(v10, v11);
                *(unsigned*)&Cl[o0] = pack_bf2(v00 - h00, v01 - h01);
                *(unsigned*)&Cl[o1] = pack_bf2(v10 - h10, v11 - h11);
            } else {
                float b0 = 0.f, b1 = 0.f;
                if (bias) { b0 = bias[c]; b1 = bias[c + 1]; }
                float2 v0 = make_float2(cc[0] + b0, cc[1] + b1);
                float2 v1 = make_float2(cc[2] + b0, cc[3] + b1);
                *(float2*)&C[(size_t)r * ldc + c]       = v0;
                *(float2*)&C[(size_t)(r + 8) * ldc + c] = v1;
            }
        }
}

// ============================================================================
// Fused scores + softmax + AV. One block per (z, 128-row m-tile).
// Loops over 16 K/V column tiles: S=QK^T (3-pass bf16), exp -> gmem P +
// smem fp16 tile + rowsum, then P@V fp16 MMA (2-pass hi/lo) accumulating
// unnormalized O. Final: rinv written, O scaled by 1/rowsum, fp32 store.
// smem ~145 KB, 1 CTA/SM, 256 threads.
// ============================================================================
#define OQH   0
#define OQL   18432
#define OKH   36864
#define OKL   55296
#define OPT   73728
#define OVH   108544
#define OVL   125952
#define OINV  143360
#define OPSUM 143872
#define FUSED_SMEM 144896
#define SAQ 72
#define SAP 136

__global__ void __launch_bounds__(256, 1)
fused_attn(const __nv_bfloat16* __restrict__ Qh, const __nv_bfloat16* __restrict__ Ql,
           const __nv_bfloat16* __restrict__ Kh, const __nv_bfloat16* __restrict__ Kl,
           const __half* __restrict__ Vh, const __half* __restrict__ Vl,
           __half* __restrict__ P, float* __restrict__ rinv,
           float* __restrict__ O)
{
    extern __shared__ char sm[];
    __nv_bfloat16* sQH = (__nv_bfloat16*)(sm + OQH);
    __nv_bfloat16* sQL = (__nv_bfloat16*)(sm + OQL);
    __nv_bfloat16* sKH = (__nv_bfloat16*)(sm + OKH);
    __nv_bfloat16* sKL = (__nv_bfloat16*)(sm + OKL);
    __half* sPT = (__half*)(sm + OPT);
    __half* sVH = (__half*)(sm + OVH);
    __half* sVL = (__half*)(sm + OVL);
    float* sInv  = (float*)(sm + OINV);
    float* sPsum = (float*)(sm + OPSUM);   // [2][128]

    const int z = blockIdx.z, bb = z >> 4, hh_ = z & 15;
    const int m0 = blockIdx.x * 128;
    const size_t qoff = (size_t)bb * SEQX * D_MODELX + (size_t)hh_ * D_HEADX;
    Qh += qoff; Ql += qoff; Kh += qoff; Kl += qoff;
    Vh += (size_t)z * D_HEADX * SEQX;
    Vl += (size_t)z * D_HEADX * SEQX;
    P  += (size_t)z * SEQX * SEQX;
    rinv += (size_t)z * SEQX;
    O  += qoff;

    const int tid  = threadIdx.x;
    const int warp = tid >> 5, lane = tid & 31;
    const int wm = (warp & 3) * 32;
    const int wn = (warp >> 2) * 64;   // scores n-offset
    const int wd = (warp >> 2) * 32;   // AV d-offset
    const int gr = lane >> 2;
    const int gc = lane & 3;
    const int ti = lane >> 3, ri = lane & 7;

    // ---- load Q tile once ----
    #pragma unroll
    for (int i = 0; i < 4; i++) {
        int idx = tid + i * 256, row = idx >> 3, c8 = idx & 7;
        size_t oa = (size_t)(m0 + row) * D_MODELX + c8 * 8;
        *(uint4*)&sQH[row * SAQ + c8 * 8] = *(const uint4*)(Qh + oa);
        *(uint4*)&sQL[row * SAQ + c8 * 8] = *(const uint4*)(Ql + oa);
    }

    // ---- fragment base addresses ----
    unsigned aHb[2], aLb[2], bHb[4], bLb[4], pab[2], vHb[2], vLb[2];
    #pragma unroll
    for (int mi = 0; mi < 2; mi++) {
        int row = wm + mi * 16 + (ti & 1) * 8 + ri;
        int col = (ti >> 1) * 8;
        aHb[mi] = smem_u32(&sQH[row * SAQ + col]);
        aLb[mi] = smem_u32(&sQL[row * SAQ + col]);
        pab[mi] = smem_u32(&sPT[row * SAP + col]);
    }
    #pragma unroll
    for (int nip = 0; nip < 4; nip++) {
        int row = wn + (nip * 2 + (ti >> 1)) * 8 + ri;
        int col = (ti & 1) * 8;
        bHb[nip] = smem_u32(&sKH[row * SAQ + col]);
        bLb[nip] = smem_u32(&sKL[row * SAQ + col]);
    }
    #pragma unroll
    for (int nip = 0; nip < 2; nip++) {
        int row = wd + (nip * 2 + (ti >> 1)) * 8 + ri;
        int col = (ti & 1) * 8;
        vHb[nip] = smem_u32(&sVH[row * SAP + col]);
        vLb[nip] = smem_u32(&sVL[row * SAP + col]);
    }

    float Oacc[2][4][4] = {};
    float rowsum[4] = {0.f, 0.f, 0.f, 0.f};

    for (int nb = 0; nb < 16; nb++) {
        const int n0 = nb * 128;
        __syncthreads();   // prior AV reads of sPT/sV done; prior scores done with sK

        // ---- load K tile (128x64 hi/lo) + V tile (64x128 hi/lo) ----
        #pragma unroll
        for (int i = 0; i < 4; i++) {
            int idx = tid + i * 256, row = idx >> 3, c8 = idx & 7;
            size_t ob = (size_t)(n0 + row) * D_MODELX + c8 * 8;
            *(uint4*)&sKH[row * SAQ + c8 * 8] = *(const uint4*)(Kh + ob);
            *(uint4*)&sKL[row * SAQ + c8 * 8] = *(const uint4*)(Kl + ob);
        }
        #pragma unroll
        for (int i = 0; i < 4; i++) {
            int idx = tid + i * 256, row = idx >> 4, c16 = idx & 15;
            size_t ov = (size_t)row * SEQX + n0 + c16 * 8;
            *(uint4*)&sVH[row * SAP + c16 * 8] = *(const uint4*)(Vh + ov);
            *(uint4*)&sVL[row * SAP + c16 * 8] = *(const uint4*)(Vl + ov);
        }
        __syncthreads();

        // ---- scores: S = QK^T, 3-pass bf16 ----
        float acc[2][8][4] = {};
        #pragma unroll
        for (int ks = 0; ks < 4; ks++) {
            const int kb2 = ks * 32;
            unsigned aH[2][4], aL[2][4], bH[4][4], bL[4][4];
            #pragma unroll
            for (int mi = 0; mi < 2; mi++) {
                LDSM_X4(aH[mi][0], aH[mi][1], aH[mi][2], aH[mi][3], aHb[mi] + kb2);
                LDSM_X4(aL[mi][0], aL[mi][1], aL[mi][2], aL[mi][3], aLb[mi] + kb2);
            }
            #pragma unroll
            for (int nip = 0; nip < 4; nip++) {
                LDSM_X4(bH[nip][0], bH[nip][1], bH[nip][2], bH[nip][3], bHb[nip] + kb2);
                LDSM_X4(bL[nip][0], bL[nip][1], bL[nip][2], bL[nip][3], bLb[nip] + kb2);
            }
            #pragma unroll
            for (int nip = 0; nip < 4; nip++)
                #pragma unroll
                for (int hh = 0; hh < 2; hh++) {
                    int ni = nip * 2 + hh;
                    unsigned b0 = bH[nip][hh * 2], b1 = bH[nip][hh * 2 + 1];
                    unsigned l0 = bL[nip][hh * 2], l1 = bL[nip][hh * 2 + 1];
                    #pragma unroll
                    for (int mi = 0; mi < 2; mi++) {
                        MMA_BF16(acc[mi][ni], aH[mi][0], aH[mi][1], aH[mi][2], aH[mi][3], b0, b1);
                        MMA_BF16(acc[mi][ni], aH[mi][0], aH[mi][1], aH[mi][2], aH[mi][3], l0, l1);
                        MMA_BF16(acc[mi][ni], aL[mi][0], aL[mi][1], aL[mi][2], aL[mi][3], b0, b1);
                    }
                }
        }

        // ---- exp -> gmem P + smem tile + rowsum ----
        #pragma unroll
        for (int mi = 0; mi < 2; mi++)
            #pragma unroll
            for (int ni = 0; ni < 8; ni++) {
                int rl = wm + mi * 16 + gr;
                int c  = wn + ni * 8 + gc * 2;
                float* cc = acc[mi][ni];
                float e0 = __expf(cc[0] * 0.125f);
                float e1 = __expf(cc[1] * 0.125f);
                float e2 = __expf(cc[2] * 0.125f);
                float e3 = __expf(cc[3] * 0.125f);
                __half2 h0 = __floats2half2_rn(e0, e1);
                __half2 h1 = __floats2half2_rn(e2, e3);
                __stcs((int*)&P[(size_t)(m0 + rl) * SEQX + n0 + c], *(int*)&h0);
                __stcs((int*)&P[(size_t)(m0 + rl + 8) * SEQX + n0 + c], *(int*)&h1);
                *(__half2*)&sPT[rl * SAP + c]       = h0;
                *(__half2*)&sPT[(rl + 8) * SAP + c] = h1;
                rowsum[mi * 2]     += e0 + e1;
                rowsum[mi * 2 + 1] += e2 + e3;
            }
        __syncthreads();

        // ---- AV: Oacc += Ptile @ Vtile^T (fp16 hi/lo, K=128) ----
        #pragma unroll
        for (int ks = 0; ks < 8; ks++) {
            const int kb2 = ks * 32;
            unsigned a[2][4], vH[2][4], vL[2][4];
            #pragma unroll
            for (int mi = 0; mi < 2; mi++)
                LDSM_X4(a[mi][0], a[mi][1], a[mi][2], a[mi][3], pab[mi] + kb2);
            #pragma unroll
            for (int nip = 0; nip < 2; nip++) {
                LDSM_X4(vH[nip][0], vH[nip][1], vH[nip][2], vH[nip][3], vHb[nip] + kb2);
                LDSM_X4(vL[nip][0], vL[nip][1], vL[nip][2], vL[nip][3], vLb[nip] + kb2);
            }
            #pragma unroll
            for (int mi = 0; mi < 2; mi++)
                #pragma unroll
                for (int nip = 0; nip < 2; nip++)
                    #pragma unroll
                    for (int hh = 0; hh < 2; hh++) {
                        int ni = nip * 2 + hh;
                        MMA_F16(Oacc[mi][ni], a[mi][0], a[mi][1], a[mi][2], a[mi][3],
                                vH[nip][hh * 2], vH[nip][hh * 2 + 1]);
                        MMA_F16(Oacc[mi][ni], a[mi][0], a[mi][1], a[mi][2], a[mi][3],
                                vL[nip][hh * 2], vL[nip][hh * 2 + 1]);
                    }
        }
    }

    // ---- finalize rowsum: quad shuffle + combine the two n-warp halves ----
    #pragma unroll
    for (int j = 0; j < 4; j++) {
        rowsum[j] += __shfl_xor_sync(0xffffffffu, rowsum[j], 1);
        rowsum[j] += __shfl_xor_sync(0xffffffffu, rowsum[j], 2);
    }
    const int wnh = warp >> 2;
    if (gc == 0) {
        sPsum[wnh * 128 + wm + gr]      = rowsum[0];
        sPsum[wnh * 128 + wm + 8 + gr]  = rowsum[1];
        sPsum[wnh * 128 + wm + 16 + gr] = rowsum[2];
        sPsum[wnh * 128 + wm + 24 + gr] = rowsum[3];
    }
    __syncthreads();
    if (tid < 128) {
        float inv = 1.0f / (sPsum[tid] + sPsum[128 + tid]);
        sInv[tid] = inv;
        rinv[m0 + tid] = inv;
    }
    __syncthreads();

    // ---- scale + store O ----
    #pragma unroll
    for (int mi = 0; mi < 2; mi++)
        #pragma unroll
        for (int ni = 0; ni < 4; ni++) {
            int rl = wm + mi * 16 + gr;
            int c  = wd + ni * 8 + gc * 2;
            float inv0 = sInv[rl], inv1 = sInv[rl + 8];
            float* cc = Oacc[mi][ni];
            *(float2*)&O[(size_t)(m0 + rl) * D_MODELX + c] =
                make_float2(cc[0] * inv0, cc[1] * inv0);
            *(float2*)&O[(size_t)(m0 + rl + 8) * D_MODELX + c] =
                make_float2(cc[2] * inv1, cc[3] * inv1);
        }
}

// ============================================================================
// avg: barrier-free head average. P holds exp(s); rinv from fused kernel.
// ============================================================================
__global__ __launch_bounds__(256)
void avg_kernel(const __half* __restrict__ P, const float* __restrict__ rinv,
                float* __restrict__ avg)
{
    const int bq = blockIdx.x;
    const int t  = threadIdx.x;
    const int b  = bq >> 11;
    const int q  = bq & 2047;

    float acc[8] = {};

    #pragma unroll 4
    for (int h = 0; h < NUM_HEADSX; ++h) {
        const int z = b * 16 + h;
        float inv = rinv[(size_t)z * SEQX + q];
        const uint4* p4 = (const uint4*)(P + ((size_t)z * SEQX + q) * SEQX);
        uint4 u = __ldcs(p4 + t);
        float2 v0 = __half22float2(*reinterpret_cast<__half2*>(&u.x));
        float2 v1 = __half22float2(*reinterpret_cast<__half2*>(&u.y));
        float2 v2 = __half22float2(*reinterpret_cast<__half2*>(&u.z));
        float2 v3 = __half22float2(*reinterpret_cast<__half2*>(&u.w));
        acc[0] += v0.x * inv; acc[1] += v0.y * inv;
        acc[2] += v1.x * inv; acc[3] += v1.y * inv;
        acc[4] += v2.x * inv; acc[5] += v2.y * inv;
        acc[6] += v3.x * inv; acc[7] += v3.y * inv;
    }

    float* a = avg + (size_t)bq * SEQX + t * 8;
    float4 o0 = make_float4(acc[0] * (1.0f / NUM_HEADSX), acc[1] * (1.0f / NUM_HEADSX),
                            acc[2] * (1.0f / NUM_HEADSX), acc[3] * (1.0f / NUM_HEADSX));
    float4 o1 = make_float4(acc[4] * (1.0f / NUM_HEADSX), acc[5] * (1.0f / NUM_HEADSX),
                            acc[6] * (1.0f / NUM_HEADSX), acc[7] * (1.0f / NUM_HEADSX));
    __stcs((float4*)a, o0);
    __stcs((float4*)(a + 4), o1);
}

// ============================================================================
// launch
// ============================================================================
extern "C" void kernel_launch(void* const* d_in, const int* in_sizes, int n_in,
                              void* d_out, int out_size)
{
    const float* x_q = (const float*)d_in[0];
    const float* x_k = (const float*)d_in[1];
    const float* x_v = (const float*)d_in[2];
    const float* Wq  = (const float*)d_in[3];
    const float* bq  = (const float*)d_in[4];
    const float* Wk  = (const float*)d_in[5];
    const float* bk  = (const float*)d_in[6];
    const float* Wv  = (const float*)d_in[7];
    const float* bv  = (const float*)d_in[8];
    const float* Wo  = (const float*)d_in[9];
    const float* bo  = (const float*)d_in[10];

    float* out = (float*)d_out;
    float* avg = out + (size_t)M_TOK * D_MODELX;

    __nv_bfloat16 *Qh, *Ql, *Kh, *Kl;
    __half *Vth, *Vtl, *P;
    float *gO, *rinv;
    cudaGetSymbolAddress((void**)&Qh, g_Qh);
    cudaGetSymbolAddress((void**)&Ql, g_Ql);
    cudaGetSymbolAddress((void**)&Kh, g_Kh);
    cudaGetSymbolAddress((void**)&Kl, g_Kl);
    cudaGetSymbolAddress((void**)&Vth, g_Vth);
    cudaGetSymbolAddress((void**)&Vtl, g_Vtl);
    cudaGetSymbolAddress((void**)&gO, g_O);
    cudaGetSymbolAddress((void**)&P, g_P);
    cudaGetSymbolAddress((void**)&rinv, g_rinv);

    cudaFuncSetAttribute(fused_attn, cudaFuncAttributeMaxDynamicSharedMemorySize,
                         FUSED_SMEM);

    dim3 blk(256);
    dim3 gproj(D_MODELX / 64, M_TOK / 128, 1);   // (16, 64)

    // 1-3) projections: Q/K -> bf16 hi/lo, V -> transposed fp16 hi/lo
    mma_gemm<5><<<gproj, blk>>>(x_q, Wq, nullptr, Qh, Ql,
                                D_MODELX, D_MODELX, D_MODELX, D_MODELX, bq);
    mma_gemm<5><<<gproj, blk>>>(x_k, Wk, nullptr, Kh, Kl,
                                D_MODELX, D_MODELX, D_MODELX, D_MODELX, bk);
    mma_gemm<3><<<gproj, blk>>>(x_v, Wv, nullptr, Vth, Vtl,
                                D_MODELX, D_MODELX, 0, D_MODELX, bv);

    // 4) fused scores + softmax + AV -> P(exp), rinv, O
    dim3 gf(SEQX / 128, 1, NZ);                  // (16, 1, 64)
    fused_attn<<<gf, blk, FUSED_SMEM>>>(Qh, Ql, Kh, Kl, Vth, Vtl, P, rinv, gO);

    // 5) head-average (barrier-free)
    avg_kernel<<<M_TOK, blk>>>(P, rinv, avg);

    // 6) output projection (fp32 out)
    mma_gemm<0><<<gproj, blk>>>(gO, Wo, out, nullptr, nullptr,
                                D_MODELX, D_MODELX, D_MODELX, D_MODELX, bo);
}